// round 1
// baseline (speedup 1.0000x reference)
#include <cuda_runtime.h>
#include <cuda_bf16.h>
#include <cstddef>

// Problem dims
constexpr int BB = 16;   // batch
constexpr int CC = 24;   // joints
constexpr int SS = 128;  // seq
constexpr int EE = 256;  // embed
constexpr int HH = 8;    // heads
constexpr int PP = 32;   // head dim
constexpr int NTOT = BB * CC * SS * EE;        // 12,582,912
constexpr int NROWS = BB * CC * SS;            // 49,152 rows of E
constexpr float LN_EPS = 1e-6f;
constexpr float INV_SQRT_P = 0.17677669529663687f; // 1/sqrt(32)

// ---------------------------------------------------------------------------
// Device scratch (no allocations allowed in kernel_launch)
// ---------------------------------------------------------------------------
__device__ float g_q[NTOT];
__device__ float g_k[NTOT];
__device__ float g_v[NTOT];
__device__ float g_o[NTOT];
__device__ float g_spat[NTOT];
__device__ float g_temp[NTOT];
__device__ float g_attn[NTOT];
__device__ float g_h[NTOT];

// ---------------------------------------------------------------------------
// Generic per-joint GEMM:
//   Y[b,c,s,f] = sum_e X[b,c,s,e] * W_c(e,f)   (+ optional bias / relu)
// X,Y layout: [B,C,S,E] row-major. For fixed c: M = B*S = 2048, N = K = 256.
// WMODE selects weight indexing:
//   0: W[c,e,f]                 (shape [C,E,E])        — Wo_s, Wo_t, ff_w1, ff_w2
//   1: W[h,c,p,e], f=(h,p)      (shape [H,C,P,E])      — Wq_s
//   2: W[h,e,p],   f=(h,p)      (shape [H,E,P])        — Wk_s, Wv_s
//   3: W[h,c,e,p], f=(h,p)      (shape [H,C,E,P])      — Wq_t, Wk_t, Wv_t
// EPI: 0 none, 1 bias+relu, 2 bias
// Tile: 128x128 output per block, BK=16, 256 threads, 8x8 micro-tile.
// ---------------------------------------------------------------------------
template <int WMODE, int EPI>
__global__ __launch_bounds__(256) void joint_gemm(
    const float* __restrict__ X, const float* __restrict__ W,
    const float* __restrict__ bias, float* __restrict__ Y)
{
    __shared__ float As[16][128];
    __shared__ float Bs[16][128];

    const int c  = blockIdx.z;
    const int m0 = blockIdx.x * 128;
    const int n0 = blockIdx.y * 128;
    const int tid = threadIdx.x;
    const int tx = tid & 15;
    const int ty = tid >> 4;

    // A-tile load mapping: thread -> (row_local = tid/2, k-chunk = (tid&1)*8)
    const int arow_l = tid >> 1;
    const int ak     = (tid & 1) * 8;
    const int arow   = m0 + arow_l;
    const int ab     = arow >> 7;      // arow / S (S=128)
    const int as     = arow & 127;
    const float* Xr = X + (((size_t)ab * CC + c) * SS + as) * EE;

    float acc[8][8];
#pragma unroll
    for (int i = 0; i < 8; ++i)
#pragma unroll
        for (int j = 0; j < 8; ++j) acc[i][j] = 0.f;

    for (int k0 = 0; k0 < EE; k0 += 16) {
        // ---- load A tile (transposed into As[k][m]) ----
        float4 av0 = *(const float4*)(Xr + k0 + ak);
        float4 av1 = *(const float4*)(Xr + k0 + ak + 4);
        As[ak + 0][arow_l] = av0.x; As[ak + 1][arow_l] = av0.y;
        As[ak + 2][arow_l] = av0.z; As[ak + 3][arow_l] = av0.w;
        As[ak + 4][arow_l] = av1.x; As[ak + 5][arow_l] = av1.y;
        As[ak + 6][arow_l] = av1.z; As[ak + 7][arow_l] = av1.w;

        // ---- load B (weight) tile into Bs[k][n] ----
        if constexpr (WMODE == 1) {
            // e-contiguous layout: load 8 consecutive e per thread at fixed f
            const int fl = tid >> 1;            // 0..127
            const int el = (tid & 1) * 8;       // 0 or 8
            const int f  = n0 + fl;
            const int h  = f >> 5, p = f & 31;
            const float* Wp = W + (((size_t)h * CC + c) * PP + p) * EE + k0 + el;
            float4 b0 = *(const float4*)(Wp);
            float4 b1 = *(const float4*)(Wp + 4);
            Bs[el + 0][fl] = b0.x; Bs[el + 1][fl] = b0.y;
            Bs[el + 2][fl] = b0.z; Bs[el + 3][fl] = b0.w;
            Bs[el + 4][fl] = b1.x; Bs[el + 5][fl] = b1.y;
            Bs[el + 6][fl] = b1.z; Bs[el + 7][fl] = b1.w;
        } else {
            // f-contiguous (within 32-wide p blocks for modes 2/3)
            const int kk = tid >> 4;            // 0..15
            const int n8 = (tid & 15) * 8;      // 0..120
            const int e  = k0 + kk;
            const int f  = n0 + n8;
            const float* Wp;
            if constexpr (WMODE == 0) {
                Wp = W + ((size_t)c * EE + e) * EE + f;
            } else if constexpr (WMODE == 2) {
                const int h = f >> 5, p = f & 31;
                Wp = W + ((size_t)h * EE + e) * PP + p;
            } else { // WMODE == 3
                const int h = f >> 5, p = f & 31;
                Wp = W + (((size_t)h * CC + c) * EE + e) * PP + p;
            }
            float4 b0 = *(const float4*)(Wp);
            float4 b1 = *(const float4*)(Wp + 4);
            *(float4*)&Bs[kk][n8]     = b0;
            *(float4*)&Bs[kk][n8 + 4] = b1;
        }
        __syncthreads();

#pragma unroll
        for (int k = 0; k < 16; ++k) {
            float4 a0 = *(const float4*)&As[k][ty * 4];
            float4 a1 = *(const float4*)&As[k][64 + ty * 4];
            float4 b0 = *(const float4*)&Bs[k][tx * 4];
            float4 b1 = *(const float4*)&Bs[k][64 + tx * 4];
            float ar[8] = {a0.x, a0.y, a0.z, a0.w, a1.x, a1.y, a1.z, a1.w};
            float br[8] = {b0.x, b0.y, b0.z, b0.w, b1.x, b1.y, b1.z, b1.w};
#pragma unroll
            for (int i = 0; i < 8; ++i)
#pragma unroll
                for (int j = 0; j < 8; ++j)
                    acc[i][j] = fmaf(ar[i], br[j], acc[i][j]);
        }
        __syncthreads();
    }

    // ---- epilogue ----
#pragma unroll
    for (int i = 0; i < 8; ++i) {
        const int r  = m0 + ((i & 4) ? 64 : 0) + ty * 4 + (i & 3);
        const int rb = r >> 7;
        const int rs = r & 127;
        float* Yr = Y + (((size_t)rb * CC + c) * SS + rs) * EE;
#pragma unroll
        for (int jq = 0; jq < 2; ++jq) {
            const int f = n0 + jq * 64 + tx * 4;
            float v0 = acc[i][jq * 4 + 0];
            float v1 = acc[i][jq * 4 + 1];
            float v2 = acc[i][jq * 4 + 2];
            float v3 = acc[i][jq * 4 + 3];
            if constexpr (EPI != 0) {
                const float* bp = bias + (size_t)c * EE + f;
                v0 += bp[0]; v1 += bp[1]; v2 += bp[2]; v3 += bp[3];
                if constexpr (EPI == 1) {
                    v0 = fmaxf(v0, 0.f); v1 = fmaxf(v1, 0.f);
                    v2 = fmaxf(v2, 0.f); v3 = fmaxf(v3, 0.f);
                }
            }
            *(float4*)(Yr + f) = make_float4(v0, v1, v2, v3);
        }
    }
}

// ---------------------------------------------------------------------------
// Spatial attention: per (b,s,h) block, attention over joints (C=24, P=32).
// q,k,v,o all in [B,C,S,E] layout with E index = h*P+p.
// grid (H, S, B), 768 threads = C*P.
// ---------------------------------------------------------------------------
__global__ __launch_bounds__(768) void spatial_attn(
    const float* __restrict__ q, const float* __restrict__ k,
    const float* __restrict__ v, float* __restrict__ o)
{
    const int h = blockIdx.x, s = blockIdx.y, b = blockIdx.z;
    __shared__ float qs[CC][PP], ks[CC][PP], vs[CC][PP];
    __shared__ float sc[CC][CC + 1];

    const int t  = threadIdx.x;
    const int cc = t >> 5;
    const int p  = t & 31;
    const size_t base = (((size_t)b * CC) * SS + s) * EE + h * PP + p;
    const size_t cstride = (size_t)SS * EE;

    qs[cc][p] = q[base + (size_t)cc * cstride];
    ks[cc][p] = k[base + (size_t)cc * cstride];
    vs[cc][p] = v[base + (size_t)cc * cstride];
    __syncthreads();

    if (t < CC * CC) {
        const int ci = t / CC, di = t % CC;
        float sum = 0.f;
#pragma unroll
        for (int pp = 0; pp < PP; ++pp)
            sum = fmaf(qs[ci][pp], ks[di][pp], sum);
        sc[ci][di] = sum * INV_SQRT_P;
    }
    __syncthreads();

    if (t < CC) {
        float mx = -1e30f;
#pragma unroll
        for (int d = 0; d < CC; ++d) mx = fmaxf(mx, sc[t][d]);
        float sm = 0.f;
#pragma unroll
        for (int d = 0; d < CC; ++d) {
            float e = __expf(sc[t][d] - mx);
            sc[t][d] = e;
            sm += e;
        }
        const float inv = 1.f / sm;
#pragma unroll
        for (int d = 0; d < CC; ++d) sc[t][d] *= inv;
    }
    __syncthreads();

    float sum = 0.f;
#pragma unroll
    for (int d = 0; d < CC; ++d)
        sum = fmaf(sc[cc][d], vs[d][p], sum);
    o[base + (size_t)cc * cstride] = sum;
}

// ---------------------------------------------------------------------------
// Temporal attention: per (b,h,c) block, attention over time (S=128, P=32).
// Dynamic smem: qT[32][132], kT[32][132] (transposed), v[128][36], sc[128][129].
// grid (C, H, B), 256 threads.
// ---------------------------------------------------------------------------
constexpr int QK_PAD = 132;
constexpr int V_PAD  = 36;
constexpr int SC_PAD = 129;
constexpr int TEMP_SMEM_FLOATS = 2 * 32 * QK_PAD + SS * V_PAD + SS * SC_PAD;
constexpr int TEMP_SMEM_BYTES  = TEMP_SMEM_FLOATS * 4;  // 118,272 B

__global__ __launch_bounds__(256) void temporal_attn(
    const float* __restrict__ q, const float* __restrict__ k,
    const float* __restrict__ v, float* __restrict__ o)
{
    extern __shared__ float smem[];
    float* qt = smem;                    // [32][QK_PAD]  qt[p][s]
    float* kt = qt + 32 * QK_PAD;        // [32][QK_PAD]  kt[p][t]
    float* vs = kt + 32 * QK_PAD;        // [128][V_PAD]  vs[t][p]
    float* sc = vs + SS * V_PAD;         // [128][SC_PAD] sc[s][t]

    const int c = blockIdx.x, h = blockIdx.y, b = blockIdx.z;
    const int tid = threadIdx.x;
    const size_t base = (((size_t)b * CC + c) * SS) * EE + h * PP;

    // ---- load q,k,v tiles ----
    for (int idx = tid; idx < SS * PP; idx += 256) {
        const int s = idx >> 5, p = idx & 31;
        const size_t g = base + (size_t)s * EE + p;
        qt[p * QK_PAD + s] = q[g];
        kt[p * QK_PAD + s] = k[g];
        vs[s * V_PAD + p]  = v[g];
    }
    __syncthreads();

    // ---- scores: 128x128 = 16x16 blocks of 8x8 per thread ----
    {
        const int tx = tid & 15;   // t-tile
        const int ty = tid >> 4;   // s-tile
        float acc[8][8];
#pragma unroll
        for (int i = 0; i < 8; ++i)
#pragma unroll
            for (int j = 0; j < 8; ++j) acc[i][j] = 0.f;

#pragma unroll 4
        for (int p = 0; p < PP; ++p) {
            float4 a0 = *(const float4*)&qt[p * QK_PAD + ty * 8];
            float4 a1 = *(const float4*)&qt[p * QK_PAD + ty * 8 + 4];
            float4 b0 = *(const float4*)&kt[p * QK_PAD + tx * 8];
            float4 b1 = *(const float4*)&kt[p * QK_PAD + tx * 8 + 4];
            float ar[8] = {a0.x, a0.y, a0.z, a0.w, a1.x, a1.y, a1.z, a1.w};
            float br[8] = {b0.x, b0.y, b0.z, b0.w, b1.x, b1.y, b1.z, b1.w};
#pragma unroll
            for (int i = 0; i < 8; ++i)
#pragma unroll
                for (int j = 0; j < 8; ++j)
                    acc[i][j] = fmaf(ar[i], br[j], acc[i][j]);
        }
#pragma unroll
        for (int i = 0; i < 8; ++i)
#pragma unroll
            for (int j = 0; j < 8; ++j)
                sc[(ty * 8 + i) * SC_PAD + tx * 8 + j] = acc[i][j] * INV_SQRT_P;
    }
    __syncthreads();

    // ---- softmax over t (rows of sc) ----
    if (tid < SS) {
        float* row = sc + tid * SC_PAD;
        float mx = -1e30f;
        for (int t2 = 0; t2 < SS; ++t2) mx = fmaxf(mx, row[t2]);
        float ssum = 0.f;
        for (int t2 = 0; t2 < SS; ++t2) {
            float e = __expf(row[t2] - mx);
            row[t2] = e;
            ssum += e;
        }
        const float inv = 1.f / ssum;
        for (int t2 = 0; t2 < SS; ++t2) row[t2] *= inv;
    }
    __syncthreads();

    // ---- o = A @ V : each thread a 4s x 4p tile ----
    {
        const int s0 = (tid >> 3) * 4;   // 0..124
        const int p0 = (tid & 7) * 4;    // 0..28
        float acc[4][4];
#pragma unroll
        for (int i = 0; i < 4; ++i)
#pragma unroll
            for (int j = 0; j < 4; ++j) acc[i][j] = 0.f;

#pragma unroll 4
        for (int t2 = 0; t2 < SS; ++t2) {
            float4 vv = *(const float4*)&vs[t2 * V_PAD + p0];
            float a0 = sc[(s0 + 0) * SC_PAD + t2];
            float a1 = sc[(s0 + 1) * SC_PAD + t2];
            float a2 = sc[(s0 + 2) * SC_PAD + t2];
            float a3 = sc[(s0 + 3) * SC_PAD + t2];
            acc[0][0] = fmaf(a0, vv.x, acc[0][0]); acc[0][1] = fmaf(a0, vv.y, acc[0][1]);
            acc[0][2] = fmaf(a0, vv.z, acc[0][2]); acc[0][3] = fmaf(a0, vv.w, acc[0][3]);
            acc[1][0] = fmaf(a1, vv.x, acc[1][0]); acc[1][1] = fmaf(a1, vv.y, acc[1][1]);
            acc[1][2] = fmaf(a1, vv.z, acc[1][2]); acc[1][3] = fmaf(a1, vv.w, acc[1][3]);
            acc[2][0] = fmaf(a2, vv.x, acc[2][0]); acc[2][1] = fmaf(a2, vv.y, acc[2][1]);
            acc[2][2] = fmaf(a2, vv.z, acc[2][2]); acc[2][3] = fmaf(a2, vv.w, acc[2][3]);
            acc[3][0] = fmaf(a3, vv.x, acc[3][0]); acc[3][1] = fmaf(a3, vv.y, acc[3][1]);
            acc[3][2] = fmaf(a3, vv.z, acc[3][2]); acc[3][3] = fmaf(a3, vv.w, acc[3][3]);
        }
#pragma unroll
        for (int i = 0; i < 4; ++i) {
            *(float4*)&o[base + (size_t)(s0 + i) * EE + p0] =
                make_float4(acc[i][0], acc[i][1], acc[i][2], acc[i][3]);
        }
    }
}

// ---------------------------------------------------------------------------
// LayerNorm kernels. One block (256 threads) per row of E=256.
// ---------------------------------------------------------------------------
__device__ __forceinline__ float blk_sum(float v, float* scratch)
{
    __syncthreads();  // protect scratch reuse from previous reduction
    const int lane = threadIdx.x & 31;
    const int w    = threadIdx.x >> 5;
#pragma unroll
    for (int off = 16; off > 0; off >>= 1)
        v += __shfl_xor_sync(0xffffffffu, v, off);
    if (lane == 0) scratch[w] = v;
    __syncthreads();
    float tot = 0.f;
#pragma unroll
    for (int i = 0; i < 8; ++i) tot += scratch[i];
    return tot;
}

// out = LN(x + a) + LN(x + b2)
__global__ __launch_bounds__(256) void dual_ln(
    const float* __restrict__ x, const float* __restrict__ a,
    const float* __restrict__ b2, const float* __restrict__ g,
    const float* __restrict__ beta, float* __restrict__ out)
{
    __shared__ float scratch[8];
    const size_t off = (size_t)blockIdx.x * EE + threadIdx.x;
    const float xv = x[off];
    const float v1 = xv + a[off];
    const float v2 = xv + b2[off];

    const float s1 = blk_sum(v1, scratch);
    const float q1 = blk_sum(v1 * v1, scratch);
    const float s2 = blk_sum(v2, scratch);
    const float q2 = blk_sum(v2 * v2, scratch);

    const float invE = 1.f / (float)EE;
    const float m1 = s1 * invE, m2 = s2 * invE;
    const float r1 = rsqrtf(fmaxf(q1 * invE - m1 * m1, 0.f) + LN_EPS);
    const float r2 = rsqrtf(fmaxf(q2 * invE - m2 * m2, 0.f) + LN_EPS);
    const float gg = g[threadIdx.x], bt = beta[threadIdx.x];
    out[off] = (v1 - m1) * r1 * gg + bt + (v2 - m2) * r2 * gg + bt;
}

// out = LN(a + f)
__global__ __launch_bounds__(256) void final_ln(
    const float* __restrict__ a, const float* __restrict__ f,
    const float* __restrict__ g, const float* __restrict__ beta,
    float* __restrict__ out)
{
    __shared__ float scratch[8];
    const size_t off = (size_t)blockIdx.x * EE + threadIdx.x;
    const float v = a[off] + f[off];
    const float s = blk_sum(v, scratch);
    const float q = blk_sum(v * v, scratch);
    const float invE = 1.f / (float)EE;
    const float m = s * invE;
    const float r = rsqrtf(fmaxf(q * invE - m * m, 0.f) + LN_EPS);
    out[off] = (v - m) * r * g[threadIdx.x] + beta[threadIdx.x];
}

// ---------------------------------------------------------------------------
// kernel_launch
// ---------------------------------------------------------------------------
extern "C" void kernel_launch(void* const* d_in, const int* in_sizes, int n_in,
                              void* d_out, int out_size)
{
    const float* x    = (const float*)d_in[0];
    const float* Wq_s = (const float*)d_in[1];
    const float* Wk_s = (const float*)d_in[2];
    const float* Wv_s = (const float*)d_in[3];
    const float* Wo_s = (const float*)d_in[4];
    const float* Wq_t = (const float*)d_in[5];
    const float* Wk_t = (const float*)d_in[6];
    const float* Wv_t = (const float*)d_in[7];
    const float* Wo_t = (const float*)d_in[8];
    const float* ln_g = (const float*)d_in[9];
    const float* ln_b = (const float*)d_in[10];
    const float* ff_w1 = (const float*)d_in[11];
    const float* ff_b1 = (const float*)d_in[12];
    const float* ff_w2 = (const float*)d_in[13];
    const float* ff_b2 = (const float*)d_in[14];
    float* out = (float*)d_out;

    float *q, *k, *v, *o, *spat, *temp, *attn, *hbuf;
    cudaGetSymbolAddress((void**)&q,    g_q);
    cudaGetSymbolAddress((void**)&k,    g_k);
    cudaGetSymbolAddress((void**)&v,    g_v);
    cudaGetSymbolAddress((void**)&o,    g_o);
    cudaGetSymbolAddress((void**)&spat, g_spat);
    cudaGetSymbolAddress((void**)&temp, g_temp);
    cudaGetSymbolAddress((void**)&attn, g_attn);
    cudaGetSymbolAddress((void**)&hbuf, g_h);

    const dim3 ggrid(BB * SS / 128, EE / 128, CC);  // (16, 2, 24)

    // ---- spatial attention branch ----
    joint_gemm<1, 0><<<ggrid, 256>>>(x, Wq_s, nullptr, q);
    joint_gemm<2, 0><<<ggrid, 256>>>(x, Wk_s, nullptr, k);
    joint_gemm<2, 0><<<ggrid, 256>>>(x, Wv_s, nullptr, v);
    spatial_attn<<<dim3(HH, SS, BB), CC * PP>>>(q, k, v, o);
    joint_gemm<0, 0><<<ggrid, 256>>>(o, Wo_s, nullptr, spat);

    // ---- temporal attention branch ----
    joint_gemm<3, 0><<<ggrid, 256>>>(x, Wq_t, nullptr, q);
    joint_gemm<3, 0><<<ggrid, 256>>>(x, Wk_t, nullptr, k);
    joint_gemm<3, 0><<<ggrid, 256>>>(x, Wv_t, nullptr, v);
    cudaFuncSetAttribute(temporal_attn,
                         cudaFuncAttributeMaxDynamicSharedMemorySize,
                         TEMP_SMEM_BYTES);
    temporal_attn<<<dim3(CC, HH, BB), 256, TEMP_SMEM_BYTES>>>(q, k, v, o);
    joint_gemm<0, 0><<<ggrid, 256>>>(o, Wo_t, nullptr, temp);

    // ---- residual + dual LN ----
    dual_ln<<<NROWS, 256>>>(x, spat, temp, ln_g, ln_b, attn);

    // ---- per-joint FF + final LN ----
    joint_gemm<0, 1><<<ggrid, 256>>>(attn, ff_w1, ff_b1, hbuf);
    joint_gemm<0, 2><<<ggrid, 256>>>(hbuf, ff_w2, ff_b2, o);
    final_ln<<<NROWS, 256>>>(attn, o, ln_g, ln_b, out);
}

// round 2
// speedup vs baseline: 1.7788x; 1.7788x over previous
#include <cuda_runtime.h>
#include <cuda_bf16.h>
#include <cstddef>

// Problem dims
constexpr int BB = 16;   // batch
constexpr int CC = 24;   // joints
constexpr int SS = 128;  // seq
constexpr int EE = 256;  // embed
constexpr int HH = 8;    // heads
constexpr int PP = 32;   // head dim
constexpr int NTOT = BB * CC * SS * EE;        // 12,582,912
constexpr int NROWS = BB * CC * SS;            // 49,152 rows of E
constexpr float LN_EPS = 1e-6f;
constexpr float INV_SQRT_P = 0.17677669529663687f; // 1/sqrt(32)

// ---------------------------------------------------------------------------
// Device scratch (no allocations allowed in kernel_launch)
// ---------------------------------------------------------------------------
__device__ float g_q[NTOT];
__device__ float g_k[NTOT];
__device__ float g_v[NTOT];
__device__ float g_o[NTOT];
__device__ float g_spat[NTOT];
__device__ float g_temp[NTOT];
__device__ float g_attn[NTOT];
__device__ float g_h[NTOT];

// ---------------------------------------------------------------------------
// Packed f32x2 helpers (sm_103a FFMA2 — 2x fp32 FMA throughput)
// ---------------------------------------------------------------------------
__device__ __forceinline__ unsigned long long pack2(float v) {
    unsigned long long r;
    asm("mov.b64 %0, {%1, %1};" : "=l"(r) : "f"(v));
    return r;
}
__device__ __forceinline__ void fma2(unsigned long long& d,
                                     unsigned long long a,
                                     unsigned long long b) {
    asm("fma.rn.f32x2 %0, %1, %2, %0;" : "+l"(d) : "l"(a), "l"(b));
}
__device__ __forceinline__ float2 unpack2(unsigned long long v) {
    float2 f;
    asm("mov.b64 {%0, %1}, %2;" : "=f"(f.x), "=f"(f.y) : "l"(v));
    return f;
}

// ---------------------------------------------------------------------------
// Generic per-joint GEMM (f32x2 packed FMA version):
//   Y[b,c,s,f] = sum_e X[b,c,s,e] * W_c(e,f)   (+ optional bias / relu)
// X,Y layout: [B,C,S,E] row-major. For fixed c: M = B*S = 2048, N = K = 256.
// WMODE selects weight indexing:
//   0: W[c,e,f]                 — Wo_s, Wo_t, ff_w1, ff_w2
//   1: W[h,c,p,e], f=(h,p)      — Wq_s   (e-contiguous)
//   2: W[h,e,p],   f=(h,p)      — Wk_s, Wv_s
//   3: W[h,c,e,p], f=(h,p)      — Wq_t, Wk_t, Wv_t
// EPI: 0 none, 1 bias+relu, 2 bias
// Block tile: 128(M) x 256(N), BK=16, 256 threads, 8x16 micro-tile (f32x2).
// ---------------------------------------------------------------------------
template <int WMODE, int EPI>
__global__ __launch_bounds__(256, 1) void joint_gemm(
    const float* __restrict__ X, const float* __restrict__ W,
    const float* __restrict__ bias, float* __restrict__ Y)
{
    __shared__ float As[16][128];
    __shared__ float Bs[16][256];

    const int c  = blockIdx.z;
    const int m0 = blockIdx.x * 128;
    const int tid = threadIdx.x;
    const int tx = tid & 15;
    const int ty = tid >> 4;

    // ---- A-tile load mapping ----
    const int arow_l = tid >> 1;          // 0..127
    const int ak     = (tid & 1) * 8;     // 0 or 8
    const int arow   = m0 + arow_l;
    const int ab     = arow >> 7;         // arow / S
    const int as     = arow & 127;
    const float* Xr = X + (((size_t)ab * CC + c) * SS + as) * EE;

    // ---- B-tile load mapping ----
    // modes 0/2/3: thread loads 16 contiguous f at one e row
    const int bkk = tid >> 4;             // 0..15 (k within tile)
    const int bn  = (tid & 15) * 16;      // 0..240
    // mode 1: two tasks, each 8 contiguous e at one f
    // task = tid + r*256; fl = task>>1 (0..255), el = (task&1)*8

    float4 aR[2];
    float4 bR[4];

    // ---- prefetch first tile into regs ----
    {
        aR[0] = *(const float4*)(Xr + ak);
        aR[1] = *(const float4*)(Xr + ak + 4);
        if constexpr (WMODE == 1) {
#pragma unroll
            for (int r = 0; r < 2; ++r) {
                const int task = tid + r * 256;
                const int fl = task >> 1, el = (task & 1) * 8;
                const int h = fl >> 5, p = fl & 31;
                const float* Wp = W + (((size_t)h * CC + c) * PP + p) * EE + el;
                bR[r * 2 + 0] = *(const float4*)(Wp);
                bR[r * 2 + 1] = *(const float4*)(Wp + 4);
            }
        } else {
            const float* Wp;
            if constexpr (WMODE == 0) {
                Wp = W + ((size_t)c * EE + bkk) * EE + bn;
            } else if constexpr (WMODE == 2) {
                const int h = bn >> 5, p = bn & 31;
                Wp = W + ((size_t)h * EE + bkk) * PP + p;
            } else {
                const int h = bn >> 5, p = bn & 31;
                Wp = W + (((size_t)h * CC + c) * EE + bkk) * PP + p;
            }
            bR[0] = *(const float4*)(Wp);
            bR[1] = *(const float4*)(Wp + 4);
            bR[2] = *(const float4*)(Wp + 8);
            bR[3] = *(const float4*)(Wp + 12);
        }
    }

    unsigned long long acc[8][8];
#pragma unroll
    for (int i = 0; i < 8; ++i)
#pragma unroll
        for (int j = 0; j < 8; ++j) acc[i][j] = 0ull;

    for (int k0 = 0; k0 < EE; k0 += 16) {
        // ---- store prefetched regs to smem ----
        As[ak + 0][arow_l] = aR[0].x; As[ak + 1][arow_l] = aR[0].y;
        As[ak + 2][arow_l] = aR[0].z; As[ak + 3][arow_l] = aR[0].w;
        As[ak + 4][arow_l] = aR[1].x; As[ak + 5][arow_l] = aR[1].y;
        As[ak + 6][arow_l] = aR[1].z; As[ak + 7][arow_l] = aR[1].w;
        if constexpr (WMODE == 1) {
#pragma unroll
            for (int r = 0; r < 2; ++r) {
                const int task = tid + r * 256;
                const int fl = task >> 1, el = (task & 1) * 8;
                Bs[el + 0][fl] = bR[r*2].x;   Bs[el + 1][fl] = bR[r*2].y;
                Bs[el + 2][fl] = bR[r*2].z;   Bs[el + 3][fl] = bR[r*2].w;
                Bs[el + 4][fl] = bR[r*2+1].x; Bs[el + 5][fl] = bR[r*2+1].y;
                Bs[el + 6][fl] = bR[r*2+1].z; Bs[el + 7][fl] = bR[r*2+1].w;
            }
        } else {
            *(float4*)&Bs[bkk][bn]      = bR[0];
            *(float4*)&Bs[bkk][bn + 4]  = bR[1];
            *(float4*)&Bs[bkk][bn + 8]  = bR[2];
            *(float4*)&Bs[bkk][bn + 12] = bR[3];
        }
        __syncthreads();

        // ---- prefetch NEXT tile (latency overlaps compute below) ----
        const int k1 = k0 + 16;
        if (k1 < EE) {
            aR[0] = *(const float4*)(Xr + k1 + ak);
            aR[1] = *(const float4*)(Xr + k1 + ak + 4);
            if constexpr (WMODE == 1) {
#pragma unroll
                for (int r = 0; r < 2; ++r) {
                    const int task = tid + r * 256;
                    const int fl = task >> 1, el = (task & 1) * 8;
                    const int h = fl >> 5, p = fl & 31;
                    const float* Wp = W + (((size_t)h * CC + c) * PP + p) * EE + k1 + el;
                    bR[r * 2 + 0] = *(const float4*)(Wp);
                    bR[r * 2 + 1] = *(const float4*)(Wp + 4);
                }
            } else {
                const float* Wp;
                if constexpr (WMODE == 0) {
                    Wp = W + ((size_t)c * EE + k1 + bkk) * EE + bn;
                } else if constexpr (WMODE == 2) {
                    const int h = bn >> 5, p = bn & 31;
                    Wp = W + ((size_t)h * EE + k1 + bkk) * PP + p;
                } else {
                    const int h = bn >> 5, p = bn & 31;
                    Wp = W + (((size_t)h * CC + c) * EE + k1 + bkk) * PP + p;
                }
                bR[0] = *(const float4*)(Wp);
                bR[1] = *(const float4*)(Wp + 4);
                bR[2] = *(const float4*)(Wp + 8);
                bR[3] = *(const float4*)(Wp + 12);
            }
        }

        // ---- compute: 8(M) x 16(N) per thread via FFMA2 ----
#pragma unroll
        for (int k = 0; k < 16; ++k) {
            float4 a0 = *(const float4*)&As[k][ty * 4];
            float4 a1 = *(const float4*)&As[k][64 + ty * 4];
            unsigned long long ar2[8];
            ar2[0] = pack2(a0.x); ar2[1] = pack2(a0.y);
            ar2[2] = pack2(a0.z); ar2[3] = pack2(a0.w);
            ar2[4] = pack2(a1.x); ar2[5] = pack2(a1.y);
            ar2[6] = pack2(a1.z); ar2[7] = pack2(a1.w);
            ulonglong2 b01 = *(const ulonglong2*)&Bs[k][tx * 4];
            ulonglong2 b23 = *(const ulonglong2*)&Bs[k][64 + tx * 4];
            ulonglong2 b45 = *(const ulonglong2*)&Bs[k][128 + tx * 4];
            ulonglong2 b67 = *(const ulonglong2*)&Bs[k][192 + tx * 4];
            unsigned long long br2[8] = {b01.x, b01.y, b23.x, b23.y,
                                         b45.x, b45.y, b67.x, b67.y};
#pragma unroll
            for (int i = 0; i < 8; ++i)
#pragma unroll
                for (int j = 0; j < 8; ++j)
                    fma2(acc[i][j], ar2[i], br2[j]);
        }
        __syncthreads();
    }

    // ---- epilogue ----
#pragma unroll
    for (int i = 0; i < 8; ++i) {
        const int r  = m0 + ((i & 4) ? 64 : 0) + ty * 4 + (i & 3);
        const int rb = r >> 7;
        const int rs = r & 127;
        float* Yr = Y + (((size_t)rb * CC + c) * SS + rs) * EE;
#pragma unroll
        for (int jq = 0; jq < 4; ++jq) {
            const int f = jq * 64 + tx * 4;
            float2 lo = unpack2(acc[i][jq * 2 + 0]);
            float2 hi = unpack2(acc[i][jq * 2 + 1]);
            float v0 = lo.x, v1 = lo.y, v2 = hi.x, v3 = hi.y;
            if constexpr (EPI != 0) {
                const float* bp = bias + (size_t)c * EE + f;
                v0 += bp[0]; v1 += bp[1]; v2 += bp[2]; v3 += bp[3];
                if constexpr (EPI == 1) {
                    v0 = fmaxf(v0, 0.f); v1 = fmaxf(v1, 0.f);
                    v2 = fmaxf(v2, 0.f); v3 = fmaxf(v3, 0.f);
                }
            }
            *(float4*)(Yr + f) = make_float4(v0, v1, v2, v3);
        }
    }
}

// ---------------------------------------------------------------------------
// Spatial attention: per (b,s,h) block, attention over joints (C=24, P=32).
// Bank-conflict fix: pad k/q tiles so the score loop's stride-32 reads of
// ks[di][pp] (di varies across the warp) hit distinct banks.
// ---------------------------------------------------------------------------
__global__ __launch_bounds__(768) void spatial_attn(
    const float* __restrict__ q, const float* __restrict__ k,
    const float* __restrict__ v, float* __restrict__ o)
{
    const int h = blockIdx.x, s = blockIdx.y, b = blockIdx.z;
    __shared__ float qs[CC][PP + 1], ks[CC][PP + 1], vs[CC][PP];
    __shared__ float sc[CC][CC + 1];

    const int t  = threadIdx.x;
    const int cc = t >> 5;
    const int p  = t & 31;
    const size_t base = (((size_t)b * CC) * SS + s) * EE + h * PP + p;
    const size_t cstride = (size_t)SS * EE;

    qs[cc][p] = q[base + (size_t)cc * cstride];
    ks[cc][p] = k[base + (size_t)cc * cstride];
    vs[cc][p] = v[base + (size_t)cc * cstride];
    __syncthreads();

    if (t < CC * CC) {
        const int ci = t / CC, di = t % CC;
        float sum = 0.f;
#pragma unroll
        for (int pp = 0; pp < PP; ++pp)
            sum = fmaf(qs[ci][pp], ks[di][pp], sum);
        sc[ci][di] = sum * INV_SQRT_P;
    }
    __syncthreads();

    if (t < CC) {
        float mx = -1e30f;
#pragma unroll
        for (int d = 0; d < CC; ++d) mx = fmaxf(mx, sc[t][d]);
        float sm = 0.f;
#pragma unroll
        for (int d = 0; d < CC; ++d) {
            float e = __expf(sc[t][d] - mx);
            sc[t][d] = e;
            sm += e;
        }
        const float inv = 1.f / sm;
#pragma unroll
        for (int d = 0; d < CC; ++d) sc[t][d] *= inv;
    }
    __syncthreads();

    float sum = 0.f;
#pragma unroll
    for (int d = 0; d < CC; ++d)
        sum = fmaf(sc[cc][d], vs[d][p], sum);
    o[base + (size_t)cc * cstride] = sum;
}

// ---------------------------------------------------------------------------
// Temporal attention: per (b,h,c) block, attention over time (S=128, P=32).
// ---------------------------------------------------------------------------
constexpr int QK_PAD = 132;
constexpr int V_PAD  = 36;
constexpr int SC_PAD = 129;
constexpr int TEMP_SMEM_FLOATS = 2 * 32 * QK_PAD + SS * V_PAD + SS * SC_PAD;
constexpr int TEMP_SMEM_BYTES  = TEMP_SMEM_FLOATS * 4;  // 118,272 B

__global__ __launch_bounds__(256) void temporal_attn(
    const float* __restrict__ q, const float* __restrict__ k,
    const float* __restrict__ v, float* __restrict__ o)
{
    extern __shared__ float smem[];
    float* qt = smem;                    // [32][QK_PAD]  qt[p][s]
    float* kt = qt + 32 * QK_PAD;        // [32][QK_PAD]  kt[p][t]
    float* vs = kt + 32 * QK_PAD;        // [128][V_PAD]  vs[t][p]
    float* sc = vs + SS * V_PAD;         // [128][SC_PAD] sc[s][t]

    const int c = blockIdx.x, h = blockIdx.y, b = blockIdx.z;
    const int tid = threadIdx.x;
    const size_t base = (((size_t)b * CC + c) * SS) * EE + h * PP;

    for (int idx = tid; idx < SS * PP; idx += 256) {
        const int s = idx >> 5, p = idx & 31;
        const size_t g = base + (size_t)s * EE + p;
        qt[p * QK_PAD + s] = q[g];
        kt[p * QK_PAD + s] = k[g];
        vs[s * V_PAD + p]  = v[g];
    }
    __syncthreads();

    {
        const int tx = tid & 15;   // t-tile
        const int ty = tid >> 4;   // s-tile
        float acc[8][8];
#pragma unroll
        for (int i = 0; i < 8; ++i)
#pragma unroll
            for (int j = 0; j < 8; ++j) acc[i][j] = 0.f;

#pragma unroll 4
        for (int p = 0; p < PP; ++p) {
            float4 a0 = *(const float4*)&qt[p * QK_PAD + ty * 8];
            float4 a1 = *(const float4*)&qt[p * QK_PAD + ty * 8 + 4];
            float4 b0 = *(const float4*)&kt[p * QK_PAD + tx * 8];
            float4 b1 = *(const float4*)&kt[p * QK_PAD + tx * 8 + 4];
            float ar[8] = {a0.x, a0.y, a0.z, a0.w, a1.x, a1.y, a1.z, a1.w};
            float br[8] = {b0.x, b0.y, b0.z, b0.w, b1.x, b1.y, b1.z, b1.w};
#pragma unroll
            for (int i = 0; i < 8; ++i)
#pragma unroll
                for (int j = 0; j < 8; ++j)
                    acc[i][j] = fmaf(ar[i], br[j], acc[i][j]);
        }
#pragma unroll
        for (int i = 0; i < 8; ++i)
#pragma unroll
            for (int j = 0; j < 8; ++j)
                sc[(ty * 8 + i) * SC_PAD + tx * 8 + j] = acc[i][j] * INV_SQRT_P;
    }
    __syncthreads();

    if (tid < SS) {
        float* row = sc + tid * SC_PAD;
        float mx = -1e30f;
        for (int t2 = 0; t2 < SS; ++t2) mx = fmaxf(mx, row[t2]);
        float ssum = 0.f;
        for (int t2 = 0; t2 < SS; ++t2) {
            float e = __expf(row[t2] - mx);
            row[t2] = e;
            ssum += e;
        }
        const float inv = 1.f / ssum;
        for (int t2 = 0; t2 < SS; ++t2) row[t2] *= inv;
    }
    __syncthreads();

    {
        const int s0 = (tid >> 3) * 4;   // 0..124
        const int p0 = (tid & 7) * 4;    // 0..28
        float acc[4][4];
#pragma unroll
        for (int i = 0; i < 4; ++i)
#pragma unroll
            for (int j = 0; j < 4; ++j) acc[i][j] = 0.f;

#pragma unroll 4
        for (int t2 = 0; t2 < SS; ++t2) {
            float4 vv = *(const float4*)&vs[t2 * V_PAD + p0];
            float a0 = sc[(s0 + 0) * SC_PAD + t2];
            float a1 = sc[(s0 + 1) * SC_PAD + t2];
            float a2 = sc[(s0 + 2) * SC_PAD + t2];
            float a3 = sc[(s0 + 3) * SC_PAD + t2];
            acc[0][0] = fmaf(a0, vv.x, acc[0][0]); acc[0][1] = fmaf(a0, vv.y, acc[0][1]);
            acc[0][2] = fmaf(a0, vv.z, acc[0][2]); acc[0][3] = fmaf(a0, vv.w, acc[0][3]);
            acc[1][0] = fmaf(a1, vv.x, acc[1][0]); acc[1][1] = fmaf(a1, vv.y, acc[1][1]);
            acc[1][2] = fmaf(a1, vv.z, acc[1][2]); acc[1][3] = fmaf(a1, vv.w, acc[1][3]);
            acc[2][0] = fmaf(a2, vv.x, acc[2][0]); acc[2][1] = fmaf(a2, vv.y, acc[2][1]);
            acc[2][2] = fmaf(a2, vv.z, acc[2][2]); acc[2][3] = fmaf(a2, vv.w, acc[2][3]);
            acc[3][0] = fmaf(a3, vv.x, acc[3][0]); acc[3][1] = fmaf(a3, vv.y, acc[3][1]);
            acc[3][2] = fmaf(a3, vv.z, acc[3][2]); acc[3][3] = fmaf(a3, vv.w, acc[3][3]);
        }
#pragma unroll
        for (int i = 0; i < 4; ++i) {
            *(float4*)&o[base + (size_t)(s0 + i) * EE + p0] =
                make_float4(acc[i][0], acc[i][1], acc[i][2], acc[i][3]);
        }
    }
}

// ---------------------------------------------------------------------------
// LayerNorm kernels. One block (256 threads) per row of E=256.
// ---------------------------------------------------------------------------
__device__ __forceinline__ float blk_sum(float v, float* scratch)
{
    __syncthreads();  // protect scratch reuse from previous reduction
    const int lane = threadIdx.x & 31;
    const int w    = threadIdx.x >> 5;
#pragma unroll
    for (int off = 16; off > 0; off >>= 1)
        v += __shfl_xor_sync(0xffffffffu, v, off);
    if (lane == 0) scratch[w] = v;
    __syncthreads();
    float tot = 0.f;
#pragma unroll
    for (int i = 0; i < 8; ++i) tot += scratch[i];
    return tot;
}

// out = LN(x + a) + LN(x + b2)
__global__ __launch_bounds__(256) void dual_ln(
    const float* __restrict__ x, const float* __restrict__ a,
    const float* __restrict__ b2, const float* __restrict__ g,
    const float* __restrict__ beta, float* __restrict__ out)
{
    __shared__ float scratch[8];
    const size_t off = (size_t)blockIdx.x * EE + threadIdx.x;
    const float xv = x[off];
    const float v1 = xv + a[off];
    const float v2 = xv + b2[off];

    const float s1 = blk_sum(v1, scratch);
    const float q1 = blk_sum(v1 * v1, scratch);
    const float s2 = blk_sum(v2, scratch);
    const float q2 = blk_sum(v2 * v2, scratch);

    const float invE = 1.f / (float)EE;
    const float m1 = s1 * invE, m2 = s2 * invE;
    const float r1 = rsqrtf(fmaxf(q1 * invE - m1 * m1, 0.f) + LN_EPS);
    const float r2 = rsqrtf(fmaxf(q2 * invE - m2 * m2, 0.f) + LN_EPS);
    const float gg = g[threadIdx.x], bt = beta[threadIdx.x];
    out[off] = (v1 - m1) * r1 * gg + bt + (v2 - m2) * r2 * gg + bt;
}

// out = LN(a + f)
__global__ __launch_bounds__(256) void final_ln(
    const float* __restrict__ a, const float* __restrict__ f,
    const float* __restrict__ g, const float* __restrict__ beta,
    float* __restrict__ out)
{
    __shared__ float scratch[8];
    const size_t off = (size_t)blockIdx.x * EE + threadIdx.x;
    const float v = a[off] + f[off];
    const float s = blk_sum(v, scratch);
    const float q = blk_sum(v * v, scratch);
    const float invE = 1.f / (float)EE;
    const float m = s * invE;
    const float r = rsqrtf(fmaxf(q * invE - m * m, 0.f) + LN_EPS);
    out[off] = (v - m) * r * g[threadIdx.x] + beta[threadIdx.x];
}

// ---------------------------------------------------------------------------
// kernel_launch
// ---------------------------------------------------------------------------
extern "C" void kernel_launch(void* const* d_in, const int* in_sizes, int n_in,
                              void* d_out, int out_size)
{
    const float* x    = (const float*)d_in[0];
    const float* Wq_s = (const float*)d_in[1];
    const float* Wk_s = (const float*)d_in[2];
    const float* Wv_s = (const float*)d_in[3];
    const float* Wo_s = (const float*)d_in[4];
    const float* Wq_t = (const float*)d_in[5];
    const float* Wk_t = (const float*)d_in[6];
    const float* Wv_t = (const float*)d_in[7];
    const float* Wo_t = (const float*)d_in[8];
    const float* ln_g = (const float*)d_in[9];
    const float* ln_b = (const float*)d_in[10];
    const float* ff_w1 = (const float*)d_in[11];
    const float* ff_b1 = (const float*)d_in[12];
    const float* ff_w2 = (const float*)d_in[13];
    const float* ff_b2 = (const float*)d_in[14];
    float* out = (float*)d_out;

    float *q, *k, *v, *o, *spat, *temp, *attn, *hbuf;
    cudaGetSymbolAddress((void**)&q,    g_q);
    cudaGetSymbolAddress((void**)&k,    g_k);
    cudaGetSymbolAddress((void**)&v,    g_v);
    cudaGetSymbolAddress((void**)&o,    g_o);
    cudaGetSymbolAddress((void**)&spat, g_spat);
    cudaGetSymbolAddress((void**)&temp, g_temp);
    cudaGetSymbolAddress((void**)&attn, g_attn);
    cudaGetSymbolAddress((void**)&hbuf, g_h);

    const dim3 ggrid(BB * SS / 128, 1, CC);  // (16, 1, 24) — N=256 per block

    // ---- spatial attention branch ----
    joint_gemm<1, 0><<<ggrid, 256>>>(x, Wq_s, nullptr, q);
    joint_gemm<2, 0><<<ggrid, 256>>>(x, Wk_s, nullptr, k);
    joint_gemm<2, 0><<<ggrid, 256>>>(x, Wv_s, nullptr, v);
    spatial_attn<<<dim3(HH, SS, BB), CC * PP>>>(q, k, v, o);
    joint_gemm<0, 0><<<ggrid, 256>>>(o, Wo_s, nullptr, spat);

    // ---- temporal attention branch ----
    joint_gemm<3, 0><<<ggrid, 256>>>(x, Wq_t, nullptr, q);
    joint_gemm<3, 0><<<ggrid, 256>>>(x, Wk_t, nullptr, k);
    joint_gemm<3, 0><<<ggrid, 256>>>(x, Wv_t, nullptr, v);
    cudaFuncSetAttribute(temporal_attn,
                         cudaFuncAttributeMaxDynamicSharedMemorySize,
                         TEMP_SMEM_BYTES);
    temporal_attn<<<dim3(CC, HH, BB), 256, TEMP_SMEM_BYTES>>>(q, k, v, o);
    joint_gemm<0, 0><<<ggrid, 256>>>(o, Wo_t, nullptr, temp);

    // ---- residual + dual LN ----
    dual_ln<<<NROWS, 256>>>(x, spat, temp, ln_g, ln_b, attn);

    // ---- per-joint FF + final LN ----
    joint_gemm<0, 1><<<ggrid, 256>>>(attn, ff_w1, ff_b1, hbuf);
    joint_gemm<0, 2><<<ggrid, 256>>>(hbuf, ff_w2, ff_b2, o);
    final_ln<<<NROWS, 256>>>(attn, o, ln_g, ln_b, out);
}

// round 4
// speedup vs baseline: 2.3340x; 1.3121x over previous
#include <cuda_runtime.h>
#include <cuda_bf16.h>
#include <cstdint>
#include <cstddef>

// Problem dims
constexpr int BB = 16, CC = 24, SS = 128, EE = 256, HH = 8, PP = 32;
constexpr int NTOT  = BB * CC * SS * EE;     // 12,582,912
constexpr int NROWS = BB * CC * SS;          // 49,152
constexpr int WELEMS = CC * EE * EE;         // 1,572,864 per weight
constexpr int NW = 10;
constexpr float LN_EPS = 1e-6f;
constexpr float INV_SQRT_P = 0.17677669529663687f;

// ---------------------------------------------------------------------------
// Device scratch
// ---------------------------------------------------------------------------
__device__ float g_q[NTOT], g_k[NTOT], g_v[NTOT];
__device__ float g_spat[NTOT], g_temp[NTOT], g_attn[NTOT], g_ffo[NTOT];
__device__ __align__(16) __nv_bfloat16 g_xh[NTOT], g_xl[NTOT];
__device__ __align__(16) __nv_bfloat16 g_ah[NTOT], g_al[NTOT];   // attn-out / attn pair
__device__ __align__(16) __nv_bfloat16 g_hh[NTOT], g_hl[NTOT];   // ff hidden pair
__device__ __align__(16) __nv_bfloat16 g_wh[NW * WELEMS], g_wl[NW * WELEMS];

// ---------------------------------------------------------------------------
// PTX helpers (baseline ISA only — no sm_103a-specific features)
// ---------------------------------------------------------------------------
__device__ __forceinline__ uint32_t smem_u32(const void* p) {
    uint32_t a;
    asm("{ .reg .u64 t; cvta.to.shared.u64 t, %1; cvt.u32.u64 %0, t; }"
        : "=r"(a) : "l"(p));
    return a;
}
__device__ __forceinline__ void cp_async16(uint32_t smem, const void* gmem) {
    asm volatile("cp.async.cg.shared.global [%0], [%1], 16;"
                 :: "r"(smem), "l"(gmem));
}
__device__ __forceinline__ void cp_commit() {
    asm volatile("cp.async.commit_group;");
}
template <int N>
__device__ __forceinline__ void cp_wait() {
    asm volatile("cp.async.wait_group %0;" :: "n"(N) : "memory");
}
__device__ __forceinline__ void ldsm_x4(uint32_t& r0, uint32_t& r1,
                                        uint32_t& r2, uint32_t& r3, uint32_t addr) {
    asm volatile("ldmatrix.sync.aligned.m8n8.x4.shared.b16 {%0,%1,%2,%3}, [%4];"
                 : "=r"(r0), "=r"(r1), "=r"(r2), "=r"(r3) : "r"(addr));
}
__device__ __forceinline__ void mma_bf16(float* d, const uint32_t* a,
                                         uint32_t b0, uint32_t b1) {
    asm volatile(
        "mma.sync.aligned.m16n8k16.row.col.f32.bf16.bf16.f32 "
        "{%0,%1,%2,%3}, {%4,%5,%6,%7}, {%8,%9}, {%0,%1,%2,%3};"
        : "+f"(d[0]), "+f"(d[1]), "+f"(d[2]), "+f"(d[3])
        : "r"(a[0]), "r"(a[1]), "r"(a[2]), "r"(a[3]), "r"(b0), "r"(b1));
}

// ---------------------------------------------------------------------------
// bf16 hi/lo split helpers
// ---------------------------------------------------------------------------
__device__ __forceinline__ void split_bf16(float x, __nv_bfloat16& h, __nv_bfloat16& l) {
    h = __float2bfloat16_rn(x);
    l = __float2bfloat16_rn(x - __bfloat162float(h));
}

__global__ __launch_bounds__(256) void split_f32_kernel(
    const float* __restrict__ src, __nv_bfloat16* __restrict__ hi,
    __nv_bfloat16* __restrict__ lo, int n4)
{
    int i = blockIdx.x * 256 + threadIdx.x;
    if (i >= n4) return;
    float4 v = ((const float4*)src)[i];
    float vv[4] = {v.x, v.y, v.z, v.w};
    __nv_bfloat16 h[4], l[4];
#pragma unroll
    for (int j = 0; j < 4; ++j) split_bf16(vv[j], h[j], l[j]);
    __nv_bfloat162* hp = (__nv_bfloat162*)hi;
    __nv_bfloat162* lp = (__nv_bfloat162*)lo;
    hp[i * 2 + 0] = __halves2bfloat162(h[0], h[1]);
    hp[i * 2 + 1] = __halves2bfloat162(h[2], h[3]);
    lp[i * 2 + 0] = __halves2bfloat162(l[0], l[1]);
    lp[i * 2 + 1] = __halves2bfloat162(l[2], l[3]);
}

// all 10 weights -> canonical W'[c][f][e] bf16 hi/lo  (K = e contiguous)
struct WPtrs { const float* p[NW]; };
__global__ __launch_bounds__(256) void convert_weights_kernel(
    WPtrs wp, __nv_bfloat16* __restrict__ wh, __nv_bfloat16* __restrict__ wl)
{
    int idx = blockIdx.x * 256 + threadIdx.x;
    if (idx >= NW * WELEMS) return;
    int w = idx / WELEMS;
    int r = idx - w * WELEMS;
    int c = r >> 16;
    int f = (r >> 8) & 255;
    int e = r & 255;
    int h = f >> 5, p = f & 31;
    int mode = (w == 3 || w >= 7) ? 0 : (w == 0 ? 1 : (w <= 2 ? 2 : 3));
    size_t src;
    if (mode == 0)      src = ((size_t)c * EE + e) * EE + f;
    else if (mode == 1) src = (((size_t)h * CC + c) * PP + p) * EE + e;
    else if (mode == 2) src = ((size_t)h * EE + e) * PP + p;
    else                src = (((size_t)h * CC + c) * EE + e) * PP + p;
    float x = wp.p[w][src];
    __nv_bfloat16 hi, lo;
    split_bf16(x, hi, lo);
    wh[idx] = hi;
    wl[idx] = lo;
}

// ---------------------------------------------------------------------------
// HMMA GEMM: Y[b,c,s,f] = sum_e A[b,c,s,e] * W'[c][f][e]
//   3-term bf16 split: Ah@Wh + Ah@Wl + Al@Wh, fp32 accumulate.
// Block: 128(M=s) x 128(N=f), BK=32, 8 warps (warp tile 32x64),
// cp.async double-buffered smem, ldmatrix operands, 80-byte row pitch
// (conflict-free LDSM: start banks {0,20,8,28,16,4,24,12}).
// EPI: 0 fp32 out; 1 bias+relu -> bf16 pair; 2 bias -> fp32
// ---------------------------------------------------------------------------
constexpr int GP = 80;                 // bytes per smem row (32 bf16 data + pad)
constexpr int T_A_HI = 0;
constexpr int T_A_LO = 128 * GP;       // 10240
constexpr int T_B_HI = 2 * 128 * GP;   // 20480
constexpr int T_B_LO = 3 * 128 * GP;   // 30720
constexpr int STAGE  = 4 * 128 * GP;   // 40960
constexpr int GEMM_SMEM = 2 * STAGE;   // 81920

template <int EPI>
__global__ __launch_bounds__(256) void gemm_mma(
    const __nv_bfloat16* __restrict__ Ah, const __nv_bfloat16* __restrict__ Al,
    const __nv_bfloat16* __restrict__ Wh, const __nv_bfloat16* __restrict__ Wl,
    const float* __restrict__ bias,
    float* __restrict__ Yf,
    __nv_bfloat16* __restrict__ Yh, __nv_bfloat16* __restrict__ Yl)
{
    extern __shared__ __align__(16) char dsm[];
    const uint32_t sbase = smem_u32(dsm);
    const int tid = threadIdx.x;
    const int wid = tid >> 5, lane = tid & 31;
    const int b = blockIdx.x, nb = blockIdx.y, c = blockIdx.z;

    const size_t abase = ((size_t)b * CC + c) * SS * EE;
    const size_t wbase = (size_t)c * EE * EE + (size_t)nb * 128 * EE;

    // ---- async load one stage (BK=32 slice at kb = stage*32) ----
    auto issue = [&](int stg) {
        const int kb = stg * 32;
        const uint32_t sb = sbase + (stg & 1) * STAGE;
#pragma unroll
        for (int j = 0; j < 2; ++j) {
            const int t2 = tid + j * 256;          // 0..511
            const int row = t2 >> 2, ch = t2 & 3;  // 128 rows x 4 chunks
            const size_t goff = (size_t)row * EE + kb + ch * 8;
            const uint32_t so = row * GP + ch * 16;
            cp_async16(sb + T_A_HI + so, Ah + abase + goff);
            cp_async16(sb + T_A_LO + so, Al + abase + goff);
            cp_async16(sb + T_B_HI + so, Wh + wbase + goff);
            cp_async16(sb + T_B_LO + so, Wl + wbase + goff);
        }
    };

    issue(0); cp_commit();
    issue(1); cp_commit();

    const int wm = wid & 3;         // 4 M-groups of 32
    const int wn = wid >> 2;        // 2 N-groups of 64
    const int g  = lane >> 3, lr = lane & 7;

    float acc[2][8][4];
#pragma unroll
    for (int mi = 0; mi < 2; ++mi)
#pragma unroll
        for (int nj = 0; nj < 8; ++nj)
#pragma unroll
            for (int r = 0; r < 4; ++r) acc[mi][nj][r] = 0.f;

    for (int it = 0; it < 8; ++it) {
        cp_wait<1>();
        __syncthreads();
        const uint32_t st = sbase + (it & 1) * STAGE;

#pragma unroll
        for (int pass = 0; pass < 3; ++pass) {
            const uint32_t Ab = st + (pass == 2 ? T_A_LO : T_A_HI);
            const uint32_t Bb = st + (pass == 1 ? T_B_LO : T_B_HI);
#pragma unroll
            for (int k16 = 0; k16 < 2; ++k16) {
                uint32_t afr[2][4];
#pragma unroll
                for (int mi = 0; mi < 2; ++mi) {
                    const int row = wm * 32 + mi * 16 + ((g & 1) << 3) + lr;
                    const uint32_t addr = Ab + row * GP + (k16 * 2 + (g >> 1)) * 16;
                    ldsm_x4(afr[mi][0], afr[mi][1], afr[mi][2], afr[mi][3], addr);
                }
                uint32_t bfr[4][4];
#pragma unroll
                for (int ni = 0; ni < 4; ++ni) {
                    const int row = wn * 64 + ni * 16 + ((g >> 1) << 3) + lr;
                    const uint32_t addr = Bb + row * GP + (k16 * 2 + (g & 1)) * 16;
                    ldsm_x4(bfr[ni][0], bfr[ni][1], bfr[ni][2], bfr[ni][3], addr);
                }
#pragma unroll
                for (int mi = 0; mi < 2; ++mi)
#pragma unroll
                    for (int nj = 0; nj < 8; ++nj)
                        mma_bf16(acc[mi][nj], afr[mi],
                                 bfr[nj >> 1][(nj & 1) * 2],
                                 bfr[nj >> 1][(nj & 1) * 2 + 1]);
            }
        }
        __syncthreads();
        if (it + 2 < 8) issue(it + 2);
        cp_commit();
    }

    // ---- epilogue ----
#pragma unroll
    for (int mi = 0; mi < 2; ++mi) {
#pragma unroll
        for (int rr = 0; rr < 2; ++rr) {
            const int m = wm * 32 + mi * 16 + (lane >> 2) + rr * 8;   // s row
            const size_t yrow = abase + (size_t)m * EE + nb * 128;
#pragma unroll
            for (int nj = 0; nj < 8; ++nj) {
                const int col = wn * 64 + nj * 8 + (lane & 3) * 2;
                float v0 = acc[mi][nj][rr * 2 + 0];
                float v1 = acc[mi][nj][rr * 2 + 1];
                if constexpr (EPI == 0) {
                    *(float2*)(Yf + yrow + col) = make_float2(v0, v1);
                } else {
                    const float* bp = bias + (size_t)c * EE + nb * 128 + col;
                    v0 += bp[0];
                    v1 += bp[1];
                    if constexpr (EPI == 1) {
                        v0 = fmaxf(v0, 0.f);
                        v1 = fmaxf(v1, 0.f);
                        __nv_bfloat16 h0, l0, h1, l1;
                        split_bf16(v0, h0, l0);
                        split_bf16(v1, h1, l1);
                        *(__nv_bfloat162*)(Yh + yrow + col) = __halves2bfloat162(h0, h1);
                        *(__nv_bfloat162*)(Yl + yrow + col) = __halves2bfloat162(l0, l1);
                    } else {
                        *(float2*)(Yf + yrow + col) = make_float2(v0, v1);
                    }
                }
            }
        }
    }
}

// ---------------------------------------------------------------------------
// Spatial attention: one block per (b,s), all 8 heads. 768 threads.
// q,k,v fp32 in [B,C,S,E]; o written as bf16 hi/lo pair.
// ---------------------------------------------------------------------------
constexpr int SA_PITCH = 257;
constexpr int SA_SMEM = (3 * CC * SA_PITCH + HH * CC * 25) * 4;  // 93,216 B

__global__ __launch_bounds__(768) void spatial_attn(
    const float* __restrict__ q, const float* __restrict__ k,
    const float* __restrict__ v, __nv_bfloat16* __restrict__ oh,
    __nv_bfloat16* __restrict__ ol)
{
    extern __shared__ float sa[];
    float* qs = sa;
    float* ks = qs + CC * SA_PITCH;
    float* vs = ks + CC * SA_PITCH;
    float* sc = vs + CC * SA_PITCH;     // [H*CC][25]

    const int s = blockIdx.x, b = blockIdx.y;
    const int t = threadIdx.x;
    const size_t gbase = ((size_t)b * CC * SS + s) * EE;
    const size_t cstride = (size_t)SS * EE;

#pragma unroll
    for (int i = 0; i < 8; ++i) {
        const int idx = t + i * 768;
        const int row = idx >> 8, e = idx & 255;
        const size_t g = gbase + row * cstride + e;
        qs[row * SA_PITCH + e] = q[g];
        ks[row * SA_PITCH + e] = k[g];
        vs[row * SA_PITCH + e] = v[g];
    }
    __syncthreads();

#pragma unroll
    for (int i = 0; i < 6; ++i) {
        const int idx = t + i * 768;
        const int h = idx / 576;
        const int r = idx - h * 576;
        const int ci = r / 24, di = r - (r / 24) * 24;
        const float* qr = qs + ci * SA_PITCH + h * 32;
        const float* kr = ks + di * SA_PITCH + h * 32;
        float sum = 0.f;
#pragma unroll
        for (int p = 0; p < 32; ++p) sum = fmaf(qr[p], kr[p], sum);
        sc[(h * CC + ci) * 25 + di] = sum * INV_SQRT_P;
    }
    __syncthreads();

    if (t < HH * CC) {
        float* row = sc + t * 25;
        float mx = -1e30f;
#pragma unroll
        for (int d = 0; d < CC; ++d) mx = fmaxf(mx, row[d]);
        float sm = 0.f;
#pragma unroll
        for (int d = 0; d < CC; ++d) { float e = __expf(row[d] - mx); row[d] = e; sm += e; }
        const float inv = 1.f / sm;
#pragma unroll
        for (int d = 0; d < CC; ++d) row[d] *= inv;
    }
    __syncthreads();

#pragma unroll
    for (int i = 0; i < 8; ++i) {
        const int idx = t + i * 768;
        const int h = idx / 768;
        const int r = idx - h * 768;
        const int cc = r >> 5, p = r & 31;
        const float* arow = sc + (h * CC + cc) * 25;
        float sum = 0.f;
#pragma unroll
        for (int d = 0; d < CC; ++d)
            sum = fmaf(arow[d], vs[d * SA_PITCH + h * 32 + p], sum);
        const size_t g = gbase + cc * cstride + h * 32 + p;
        __nv_bfloat16 hi, lo;
        split_bf16(sum, hi, lo);
        oh[g] = hi;
        ol[g] = lo;
    }
}

// ---------------------------------------------------------------------------
// Temporal attention: per (b,h,c) block, attention over time. o -> bf16 pair.
// ---------------------------------------------------------------------------
constexpr int QK_PAD = 132, V_PAD = 36, SC_PAD = 129;
constexpr int TEMP_SMEM_BYTES = (2 * 32 * QK_PAD + SS * V_PAD + SS * SC_PAD) * 4;

__global__ __launch_bounds__(256) void temporal_attn(
    const float* __restrict__ q, const float* __restrict__ k,
    const float* __restrict__ v, __nv_bfloat16* __restrict__ oh,
    __nv_bfloat16* __restrict__ ol)
{
    extern __shared__ float smem[];
    float* qt = smem;
    float* kt = qt + 32 * QK_PAD;
    float* vs = kt + 32 * QK_PAD;
    float* sc = vs + SS * V_PAD;

    const int c = blockIdx.x, h = blockIdx.y, b = blockIdx.z;
    const int tid = threadIdx.x;
    const size_t base = (((size_t)b * CC + c) * SS) * EE + h * PP;

    for (int idx = tid; idx < SS * PP; idx += 256) {
        const int s = idx >> 5, p = idx & 31;
        const size_t g = base + (size_t)s * EE + p;
        qt[p * QK_PAD + s] = q[g];
        kt[p * QK_PAD + s] = k[g];
        vs[s * V_PAD + p]  = v[g];
    }
    __syncthreads();

    {
        const int tx = tid & 15, ty = tid >> 4;
        float acc[8][8];
#pragma unroll
        for (int i = 0; i < 8; ++i)
#pragma unroll
            for (int j = 0; j < 8; ++j) acc[i][j] = 0.f;
#pragma unroll 4
        for (int p = 0; p < PP; ++p) {
            float4 a0 = *(const float4*)&qt[p * QK_PAD + ty * 8];
            float4 a1 = *(const float4*)&qt[p * QK_PAD + ty * 8 + 4];
            float4 b0 = *(const float4*)&kt[p * QK_PAD + tx * 8];
            float4 b1 = *(const float4*)&kt[p * QK_PAD + tx * 8 + 4];
            float ar[8] = {a0.x, a0.y, a0.z, a0.w, a1.x, a1.y, a1.z, a1.w};
            float br[8] = {b0.x, b0.y, b0.z, b0.w, b1.x, b1.y, b1.z, b1.w};
#pragma unroll
            for (int i = 0; i < 8; ++i)
#pragma unroll
                for (int j = 0; j < 8; ++j)
                    acc[i][j] = fmaf(ar[i], br[j], acc[i][j]);
        }
#pragma unroll
        for (int i = 0; i < 8; ++i)
#pragma unroll
            for (int j = 0; j < 8; ++j)
                sc[(ty * 8 + i) * SC_PAD + tx * 8 + j] = acc[i][j] * INV_SQRT_P;
    }
    __syncthreads();

    if (tid < SS) {
        float* row = sc + tid * SC_PAD;
        float mx = -1e30f;
        for (int t2 = 0; t2 < SS; ++t2) mx = fmaxf(mx, row[t2]);
        float ssum = 0.f;
        for (int t2 = 0; t2 < SS; ++t2) { float e = __expf(row[t2] - mx); row[t2] = e; ssum += e; }
        const float inv = 1.f / ssum;
        for (int t2 = 0; t2 < SS; ++t2) row[t2] *= inv;
    }
    __syncthreads();

    {
        const int s0 = (tid >> 3) * 4;
        const int p0 = (tid & 7) * 4;
        float acc[4][4];
#pragma unroll
        for (int i = 0; i < 4; ++i)
#pragma unroll
            for (int j = 0; j < 4; ++j) acc[i][j] = 0.f;
#pragma unroll 4
        for (int t2 = 0; t2 < SS; ++t2) {
            float4 vv = *(const float4*)&vs[t2 * V_PAD + p0];
            float a0 = sc[(s0 + 0) * SC_PAD + t2];
            float a1 = sc[(s0 + 1) * SC_PAD + t2];
            float a2 = sc[(s0 + 2) * SC_PAD + t2];
            float a3 = sc[(s0 + 3) * SC_PAD + t2];
            acc[0][0] = fmaf(a0, vv.x, acc[0][0]); acc[0][1] = fmaf(a0, vv.y, acc[0][1]);
            acc[0][2] = fmaf(a0, vv.z, acc[0][2]); acc[0][3] = fmaf(a0, vv.w, acc[0][3]);
            acc[1][0] = fmaf(a1, vv.x, acc[1][0]); acc[1][1] = fmaf(a1, vv.y, acc[1][1]);
            acc[1][2] = fmaf(a1, vv.z, acc[1][2]); acc[1][3] = fmaf(a1, vv.w, acc[1][3]);
            acc[2][0] = fmaf(a2, vv.x, acc[2][0]); acc[2][1] = fmaf(a2, vv.y, acc[2][1]);
            acc[2][2] = fmaf(a2, vv.z, acc[2][2]); acc[2][3] = fmaf(a2, vv.w, acc[2][3]);
            acc[3][0] = fmaf(a3, vv.x, acc[3][0]); acc[3][1] = fmaf(a3, vv.y, acc[3][1]);
            acc[3][2] = fmaf(a3, vv.z, acc[3][2]); acc[3][3] = fmaf(a3, vv.w, acc[3][3]);
        }
#pragma unroll
        for (int i = 0; i < 4; ++i)
#pragma unroll
            for (int j = 0; j < 4; ++j) {
                const size_t g = base + (size_t)(s0 + i) * EE + p0 + j;
                __nv_bfloat16 hi, lo;
                split_bf16(acc[i][j], hi, lo);
                oh[g] = hi;
                ol[g] = lo;
            }
    }
}

// ---------------------------------------------------------------------------
// LayerNorm kernels
// ---------------------------------------------------------------------------
__device__ __forceinline__ float blk_sum(float v, float* scratch)
{
    __syncthreads();
    const int lane = threadIdx.x & 31, w = threadIdx.x >> 5;
#pragma unroll
    for (int off = 16; off > 0; off >>= 1)
        v += __shfl_xor_sync(0xffffffffu, v, off);
    if (lane == 0) scratch[w] = v;
    __syncthreads();
    float tot = 0.f;
#pragma unroll
    for (int i = 0; i < 8; ++i) tot += scratch[i];
    return tot;
}

__global__ __launch_bounds__(256) void dual_ln(
    const float* __restrict__ x, const float* __restrict__ a,
    const float* __restrict__ b2, const float* __restrict__ g,
    const float* __restrict__ beta, float* __restrict__ out,
    __nv_bfloat16* __restrict__ oh, __nv_bfloat16* __restrict__ ol)
{
    __shared__ float scratch[8];
    const size_t off = (size_t)blockIdx.x * EE + threadIdx.x;
    const float xv = x[off];
    const float v1 = xv + a[off];
    const float v2 = xv + b2[off];

    const float s1 = blk_sum(v1, scratch);
    const float q1 = blk_sum(v1 * v1, scratch);
    const float s2 = blk_sum(v2, scratch);
    const float q2 = blk_sum(v2 * v2, scratch);

    const float invE = 1.f / (float)EE;
    const float m1 = s1 * invE, m2 = s2 * invE;
    const float r1 = rsqrtf(fmaxf(q1 * invE - m1 * m1, 0.f) + LN_EPS);
    const float r2 = rsqrtf(fmaxf(q2 * invE - m2 * m2, 0.f) + LN_EPS);
    const float gg = g[threadIdx.x], bt = beta[threadIdx.x];
    const float o = (v1 - m1) * r1 * gg + bt + (v2 - m2) * r2 * gg + bt;
    out[off] = o;
    __nv_bfloat16 hi, lo;
    split_bf16(o, hi, lo);
    oh[off] = hi;
    ol[off] = lo;
}

__global__ __launch_bounds__(256) void final_ln(
    const float* __restrict__ a, const float* __restrict__ f,
    const float* __restrict__ g, const float* __restrict__ beta,
    float* __restrict__ out)
{
    __shared__ float scratch[8];
    const size_t off = (size_t)blockIdx.x * EE + threadIdx.x;
    const float v = a[off] + f[off];
    const float s = blk_sum(v, scratch);
    const float q = blk_sum(v * v, scratch);
    const float invE = 1.f / (float)EE;
    const float m = s * invE;
    const float r = rsqrtf(fmaxf(q * invE - m * m, 0.f) + LN_EPS);
    out[off] = (v - m) * r * g[threadIdx.x] + beta[threadIdx.x];
}

// ---------------------------------------------------------------------------
// kernel_launch
// ---------------------------------------------------------------------------
extern "C" void kernel_launch(void* const* d_in, const int* in_sizes, int n_in,
                              void* d_out, int out_size)
{
    const float* x    = (const float*)d_in[0];
    const float* ln_g = (const float*)d_in[9];
    const float* ln_b = (const float*)d_in[10];
    const float* ff_b1 = (const float*)d_in[12];
    const float* ff_b2 = (const float*)d_in[14];
    float* out = (float*)d_out;

    float *q, *k, *v, *spat, *temp, *attn, *ffo;
    __nv_bfloat16 *xh, *xl, *ah, *al, *hh, *hl, *wh, *wl;
    cudaGetSymbolAddress((void**)&q,    g_q);
    cudaGetSymbolAddress((void**)&k,    g_k);
    cudaGetSymbolAddress((void**)&v,    g_v);
    cudaGetSymbolAddress((void**)&spat, g_spat);
    cudaGetSymbolAddress((void**)&temp, g_temp);
    cudaGetSymbolAddress((void**)&attn, g_attn);
    cudaGetSymbolAddress((void**)&ffo,  g_ffo);
    cudaGetSymbolAddress((void**)&xh, g_xh);
    cudaGetSymbolAddress((void**)&xl, g_xl);
    cudaGetSymbolAddress((void**)&ah, g_ah);
    cudaGetSymbolAddress((void**)&al, g_al);
    cudaGetSymbolAddress((void**)&hh, g_hh);
    cudaGetSymbolAddress((void**)&hl, g_hl);
    cudaGetSymbolAddress((void**)&wh, g_wh);
    cudaGetSymbolAddress((void**)&wl, g_wl);

    cudaFuncSetAttribute(gemm_mma<0>, cudaFuncAttributeMaxDynamicSharedMemorySize, GEMM_SMEM);
    cudaFuncSetAttribute(gemm_mma<1>, cudaFuncAttributeMaxDynamicSharedMemorySize, GEMM_SMEM);
    cudaFuncSetAttribute(gemm_mma<2>, cudaFuncAttributeMaxDynamicSharedMemorySize, GEMM_SMEM);
    cudaFuncSetAttribute(spatial_attn, cudaFuncAttributeMaxDynamicSharedMemorySize, SA_SMEM);
    cudaFuncSetAttribute(temporal_attn, cudaFuncAttributeMaxDynamicSharedMemorySize, TEMP_SMEM_BYTES);

    // ---- conversions ----
    split_f32_kernel<<<NTOT / 4 / 256, 256>>>(x, xh, xl, NTOT / 4);
    WPtrs wp;
    wp.p[0] = (const float*)d_in[1];  // Wq_s
    wp.p[1] = (const float*)d_in[2];  // Wk_s
    wp.p[2] = (const float*)d_in[3];  // Wv_s
    wp.p[3] = (const float*)d_in[4];  // Wo_s
    wp.p[4] = (const float*)d_in[5];  // Wq_t
    wp.p[5] = (const float*)d_in[6];  // Wk_t
    wp.p[6] = (const float*)d_in[7];  // Wv_t
    wp.p[7] = (const float*)d_in[8];  // Wo_t
    wp.p[8] = (const float*)d_in[11]; // ff_w1
    wp.p[9] = (const float*)d_in[13]; // ff_w2
    convert_weights_kernel<<<(NW * WELEMS + 255) / 256, 256>>>(wp, wh, wl);

    const dim3 ggrid(BB, 2, CC);  // (b, n-block, c) = 768 blocks

    // ---- spatial attention branch ----
    gemm_mma<0><<<ggrid, 256, GEMM_SMEM>>>(xh, xl, wh + 0*(size_t)WELEMS, wl + 0*(size_t)WELEMS, nullptr, q, nullptr, nullptr);
    gemm_mma<0><<<ggrid, 256, GEMM_SMEM>>>(xh, xl, wh + 1*(size_t)WELEMS, wl + 1*(size_t)WELEMS, nullptr, k, nullptr, nullptr);
    gemm_mma<0><<<ggrid, 256, GEMM_SMEM>>>(xh, xl, wh + 2*(size_t)WELEMS, wl + 2*(size_t)WELEMS, nullptr, v, nullptr, nullptr);
    spatial_attn<<<dim3(SS, BB), 768, SA_SMEM>>>(q, k, v, ah, al);
    gemm_mma<0><<<ggrid, 256, GEMM_SMEM>>>(ah, al, wh + 3*(size_t)WELEMS, wl + 3*(size_t)WELEMS, nullptr, spat, nullptr, nullptr);

    // ---- temporal attention branch ----
    gemm_mma<0><<<ggrid, 256, GEMM_SMEM>>>(xh, xl, wh + 4*(size_t)WELEMS, wl + 4*(size_t)WELEMS, nullptr, q, nullptr, nullptr);
    gemm_mma<0><<<ggrid, 256, GEMM_SMEM>>>(xh, xl, wh + 5*(size_t)WELEMS, wl + 5*(size_t)WELEMS, nullptr, k, nullptr, nullptr);
    gemm_mma<0><<<ggrid, 256, GEMM_SMEM>>>(xh, xl, wh + 6*(size_t)WELEMS, wl + 6*(size_t)WELEMS, nullptr, v, nullptr, nullptr);
    temporal_attn<<<dim3(CC, HH, BB), 256, TEMP_SMEM_BYTES>>>(q, k, v, ah, al);
    gemm_mma<0><<<ggrid, 256, GEMM_SMEM>>>(ah, al, wh + 7*(size_t)WELEMS, wl + 7*(size_t)WELEMS, nullptr, temp, nullptr, nullptr);

    // ---- residual + dual LN (emits attn fp32 + bf16 pair) ----
    dual_ln<<<NROWS, 256>>>(x, spat, temp, ln_g, ln_b, attn, ah, al);

    // ---- per-joint FF + final LN ----
    gemm_mma<1><<<ggrid, 256, GEMM_SMEM>>>(ah, al, wh + 8*(size_t)WELEMS, wl + 8*(size_t)WELEMS, ff_b1, nullptr, hh, hl);
    gemm_mma<2><<<ggrid, 256, GEMM_SMEM>>>(hh, hl, wh + 9*(size_t)WELEMS, wl + 9*(size_t)WELEMS, ff_b2, ffo, nullptr, nullptr);
    final_ln<<<NROWS, 256>>>(attn, ffo, ln_g, ln_b, out);
}

// round 5
// speedup vs baseline: 2.6138x; 1.1199x over previous
#include <cuda_runtime.h>
#include <cuda_bf16.h>
#include <cstdint>
#include <cstddef>

// Problem dims
constexpr int BB = 16, CC = 24, SS = 128, EE = 256, HH = 8, PP = 32;
constexpr int NTOT  = BB * CC * SS * EE;     // 12,582,912
constexpr int NROWS = BB * CC * SS;          // 49,152
constexpr int WELEMS = CC * EE * EE;         // 1,572,864 per weight
constexpr int NW = 10;
constexpr float LN_EPS = 1e-6f;
constexpr float INV_SQRT_P = 0.17677669529663687f;

// ---------------------------------------------------------------------------
// Device scratch
// ---------------------------------------------------------------------------
__device__ float g_qs[NTOT], g_ks[NTOT], g_vs[NTOT];
__device__ float g_qt[NTOT], g_kt[NTOT], g_vt[NTOT];
__device__ float g_spat[NTOT], g_temp[NTOT], g_attn[NTOT], g_ffo[NTOT];
__device__ __align__(16) __nv_bfloat16 g_xh[NTOT], g_xl[NTOT];
__device__ __align__(16) __nv_bfloat16 g_ah[NTOT], g_al[NTOT];   // spatial-out / attn pair
__device__ __align__(16) __nv_bfloat16 g_hh[NTOT], g_hl[NTOT];   // temporal-out / ff hidden pair
__device__ __align__(16) __nv_bfloat16 g_wh[NW * WELEMS], g_wl[NW * WELEMS];

// ---------------------------------------------------------------------------
// PTX helpers (baseline ISA only)
// ---------------------------------------------------------------------------
__device__ __forceinline__ uint32_t smem_u32(const void* p) {
    uint32_t a;
    asm("{ .reg .u64 t; cvta.to.shared.u64 t, %1; cvt.u32.u64 %0, t; }"
        : "=r"(a) : "l"(p));
    return a;
}
__device__ __forceinline__ void cp_async16(uint32_t smem, const void* gmem) {
    asm volatile("cp.async.cg.shared.global [%0], [%1], 16;"
                 :: "r"(smem), "l"(gmem));
}
__device__ __forceinline__ void cp_commit() {
    asm volatile("cp.async.commit_group;");
}
template <int N>
__device__ __forceinline__ void cp_wait() {
    asm volatile("cp.async.wait_group %0;" :: "n"(N) : "memory");
}
__device__ __forceinline__ void ldsm_x4(uint32_t& r0, uint32_t& r1,
                                        uint32_t& r2, uint32_t& r3, uint32_t addr) {
    asm volatile("ldmatrix.sync.aligned.m8n8.x4.shared.b16 {%0,%1,%2,%3}, [%4];"
                 : "=r"(r0), "=r"(r1), "=r"(r2), "=r"(r3) : "r"(addr));
}
__device__ __forceinline__ void mma_bf16(float* d, const uint32_t* a,
                                         uint32_t b0, uint32_t b1) {
    asm volatile(
        "mma.sync.aligned.m16n8k16.row.col.f32.bf16.bf16.f32 "
        "{%0,%1,%2,%3}, {%4,%5,%6,%7}, {%8,%9}, {%0,%1,%2,%3};"
        : "+f"(d[0]), "+f"(d[1]), "+f"(d[2]), "+f"(d[3])
        : "r"(a[0]), "r"(a[1]), "r"(a[2]), "r"(a[3]), "r"(b0), "r"(b1));
}
// packed f32x2
__device__ __forceinline__ unsigned long long pack2(float v) {
    unsigned long long r;
    asm("mov.b64 %0, {%1, %1};" : "=l"(r) : "f"(v));
    return r;
}
__device__ __forceinline__ void fma2(unsigned long long& d,
                                     unsigned long long a, unsigned long long b) {
    asm("fma.rn.f32x2 %0, %1, %2, %0;" : "+l"(d) : "l"(a), "l"(b));
}
__device__ __forceinline__ float2 unpack2(unsigned long long v) {
    float2 f;
    asm("mov.b64 {%0, %1}, %2;" : "=f"(f.x), "=f"(f.y) : "l"(v));
    return f;
}

// ---------------------------------------------------------------------------
// bf16 hi/lo split helpers
// ---------------------------------------------------------------------------
__device__ __forceinline__ void split_bf16(float x, __nv_bfloat16& h, __nv_bfloat16& l) {
    h = __float2bfloat16_rn(x);
    l = __float2bfloat16_rn(x - __bfloat162float(h));
}

__global__ __launch_bounds__(256) void split_f32_kernel(
    const float* __restrict__ src, __nv_bfloat16* __restrict__ hi,
    __nv_bfloat16* __restrict__ lo, int n4)
{
    int i = blockIdx.x * 256 + threadIdx.x;
    if (i >= n4) return;
    float4 v = ((const float4*)src)[i];
    float vv[4] = {v.x, v.y, v.z, v.w};
    __nv_bfloat16 h[4], l[4];
#pragma unroll
    for (int j = 0; j < 4; ++j) split_bf16(vv[j], h[j], l[j]);
    __nv_bfloat162* hp = (__nv_bfloat162*)hi;
    __nv_bfloat162* lp = (__nv_bfloat162*)lo;
    hp[i * 2 + 0] = __halves2bfloat162(h[0], h[1]);
    hp[i * 2 + 1] = __halves2bfloat162(h[2], h[3]);
    lp[i * 2 + 0] = __halves2bfloat162(l[0], l[1]);
    lp[i * 2 + 1] = __halves2bfloat162(l[2], l[3]);
}

// ---------------------------------------------------------------------------
// Weight conversion, coalesced: 32x32 (e,f) tiles via smem transpose.
// Canonical output W'[w][c][f][e], e contiguous.
// grid (64 tiles, CC, NW); block 256.
// ---------------------------------------------------------------------------
struct WPtrs { const float* p[NW]; };

__global__ __launch_bounds__(256) void convert_weights_t(
    WPtrs wp, __nv_bfloat16* __restrict__ wh, __nv_bfloat16* __restrict__ wl)
{
    __shared__ float tile[32][33];
    const int w = blockIdx.z, c = blockIdx.y;
    const int eb = blockIdx.x & 7, fb = blockIdx.x >> 3;
    const int mode = (w == 3 || w >= 7) ? 0 : (w == 0 ? 1 : (w <= 2 ? 2 : 3));
    const int t = threadIdx.x;
    const int col = t & 31, r0 = t >> 5;
    const float* W = wp.p[w];

#pragma unroll
    for (int i = 0; i < 4; ++i) {
        const int row = r0 + i * 8;
        float v;
        if (mode == 0) {
            const int e = eb * 32 + row, f = fb * 32 + col;
            v = W[((size_t)c * EE + e) * EE + f];              // [e][f]
        } else if (mode == 1) {
            const int f = fb * 32 + row, e = eb * 32 + col;
            const int h = fb, p = f & 31;
            v = W[(((size_t)h * CC + c) * PP + p) * EE + e];   // [f][e]
        } else if (mode == 2) {
            const int e = eb * 32 + row, p = col, h = fb;
            v = W[((size_t)h * EE + e) * PP + p];              // [e][f]
        } else {
            const int e = eb * 32 + row, p = col, h = fb;
            v = W[(((size_t)h * CC + c) * EE + e) * PP + p];   // [e][f]
        }
        tile[row][col] = v;
    }
    __syncthreads();

#pragma unroll
    for (int i = 0; i < 4; ++i) {
        const int fr = r0 + i * 8;
        const int f = fb * 32 + fr;
        const int e = eb * 32 + col;
        const float v = (mode == 1) ? tile[fr][col] : tile[col][fr];
        __nv_bfloat16 hi, lo;
        split_bf16(v, hi, lo);
        const size_t o = (size_t)w * WELEMS + ((size_t)c << 16) + (size_t)f * EE + e;
        wh[o] = hi;
        wl[o] = lo;
    }
}

// ---------------------------------------------------------------------------
// Fused QKVx6 GEMM: A = (xh,xl) kept RESIDENT in smem for full K=256;
// streams 48 B-stages (6 weights x 8 K-chunks of 32) with triple buffering.
// Block: M=128(one b,c) x N=128(nb), 8 warps, warp tile 32x64.
// 3-pass bf16 split per stage. Outputs 6 fp32 tensors.
// ---------------------------------------------------------------------------
constexpr int AP = 528;                        // A row pitch bytes (512 data + 16)
constexpr int QA_HI = 0;
constexpr int QA_LO = 128 * AP;                // 67584
constexpr int QB0   = 2 * 128 * AP;            // 135168
constexpr int QB_STG = 20480;                  // Wh(10240)+Wl(10240) per stage
constexpr int QKV_SMEM = QB0 + 3 * QB_STG;     // 196608

constexpr int GP = 80;                         // B row pitch bytes

struct Out6 { float* y[6]; };

__global__ __launch_bounds__(256) void gemm_qkv6(
    const __nv_bfloat16* __restrict__ xh, const __nv_bfloat16* __restrict__ xl,
    const __nv_bfloat16* __restrict__ whB, const __nv_bfloat16* __restrict__ wlB,
    Out6 outs)
{
    extern __shared__ __align__(16) char dsm[];
    const uint32_t sbase = smem_u32(dsm);
    const int tid = threadIdx.x;
    const int wid = tid >> 5, lane = tid & 31;
    const int b = blockIdx.x, nb = blockIdx.y, c = blockIdx.z;

    const size_t abase = ((size_t)b * CC + c) * SS * EE;

    // ---- load A (both hi/lo, full K) ----
#pragma unroll
    for (int i = 0; i < 16; ++i) {
        const int t2 = tid + i * 256;          // 0..4095
        const int row = t2 >> 5, ch = t2 & 31; // 128 rows x 32 chunks of 16B
        const size_t goff = (size_t)row * EE + ch * 8;
        const uint32_t so = row * AP + ch * 16;
        cp_async16(sbase + QA_HI + so, xh + abase + goff);
        cp_async16(sbase + QA_LO + so, xl + abase + goff);
    }
    cp_commit();

    // ---- B stage issue (stage 0..47: weight = stage/8, kb = (stage%8)*32) ----
    auto issueB = [&](int stage) {
        const int w = stage >> 3, kb = (stage & 7) * 32;
        const int wg = w + (w >= 3);           // 0,1,2,4,5,6
        const __nv_bfloat16* Wh = whB + (size_t)wg * WELEMS + ((size_t)c << 16)
                                + (size_t)nb * 128 * EE;
        const __nv_bfloat16* Wl = wlB + (size_t)wg * WELEMS + ((size_t)c << 16)
                                + (size_t)nb * 128 * EE;
        const uint32_t sb = sbase + QB0 + (stage % 3) * QB_STG;
#pragma unroll
        for (int j = 0; j < 2; ++j) {
            const int t2 = tid + j * 256;
            const int row = t2 >> 2, ch = t2 & 3;
            const size_t goff = (size_t)row * EE + kb + ch * 8;
            const uint32_t so = row * GP + ch * 16;
            cp_async16(sb + so, Wh + goff);
            cp_async16(sb + 10240 + so, Wl + goff);
        }
    };
    issueB(0); cp_commit();
    issueB(1); cp_commit();
    issueB(2); cp_commit();

    const int wm = wid & 3, wn = wid >> 2;
    const int g = lane >> 3, lr = lane & 7;

    for (int w = 0; w < 6; ++w) {
        float acc[2][8][4];
#pragma unroll
        for (int mi = 0; mi < 2; ++mi)
#pragma unroll
            for (int nj = 0; nj < 8; ++nj)
#pragma unroll
                for (int r = 0; r < 4; ++r) acc[mi][nj][r] = 0.f;

        for (int it = 0; it < 8; ++it) {
            const int stage = w * 8 + it;
            cp_wait<2>();
            __syncthreads();
            const uint32_t Bst = sbase + QB0 + (stage % 3) * QB_STG;

#pragma unroll
            for (int pass = 0; pass < 3; ++pass) {
                const uint32_t Ab = sbase + (pass == 2 ? QA_LO : QA_HI);
                const uint32_t Bb = Bst + (pass == 1 ? 10240 : 0);
#pragma unroll
                for (int k16 = 0; k16 < 2; ++k16) {
                    uint32_t afr[2][4];
#pragma unroll
                    for (int mi = 0; mi < 2; ++mi) {
                        const int row = wm * 32 + mi * 16 + ((g & 1) << 3) + lr;
                        const uint32_t addr =
                            Ab + row * AP + (it * 4 + k16 * 2 + (g >> 1)) * 16;
                        ldsm_x4(afr[mi][0], afr[mi][1], afr[mi][2], afr[mi][3], addr);
                    }
                    uint32_t bfr[4][4];
#pragma unroll
                    for (int ni = 0; ni < 4; ++ni) {
                        const int row = wn * 64 + ni * 16 + ((g >> 1) << 3) + lr;
                        const uint32_t addr = Bb + row * GP + (k16 * 2 + (g & 1)) * 16;
                        ldsm_x4(bfr[ni][0], bfr[ni][1], bfr[ni][2], bfr[ni][3], addr);
                    }
#pragma unroll
                    for (int mi = 0; mi < 2; ++mi)
#pragma unroll
                        for (int nj = 0; nj < 8; ++nj)
                            mma_bf16(acc[mi][nj], afr[mi],
                                     bfr[nj >> 1][(nj & 1) * 2],
                                     bfr[nj >> 1][(nj & 1) * 2 + 1]);
                }
            }
            __syncthreads();
            if (stage + 3 < 48) issueB(stage + 3);
            cp_commit();
        }

        // ---- epilogue for weight w ----
        float* Yf = outs.y[w];
#pragma unroll
        for (int mi = 0; mi < 2; ++mi)
#pragma unroll
            for (int rr = 0; rr < 2; ++rr) {
                const int m = wm * 32 + mi * 16 + (lane >> 2) + rr * 8;
                const size_t yrow = abase + (size_t)m * EE + nb * 128;
#pragma unroll
                for (int nj = 0; nj < 8; ++nj) {
                    const int colo = wn * 64 + nj * 8 + (lane & 3) * 2;
                    *(float2*)(Yf + yrow + colo) =
                        make_float2(acc[mi][nj][rr * 2 + 0], acc[mi][nj][rr * 2 + 1]);
                }
            }
    }
}

// ---------------------------------------------------------------------------
// Generic HMMA GEMM (Wo / FF): 128x128, 3-stage cp.async pipeline.
// EPI: 0 fp32 out; 1 bias+relu -> bf16 pair; 2 bias -> fp32
// ---------------------------------------------------------------------------
constexpr int T_A_HI = 0;
constexpr int T_A_LO = 128 * GP;
constexpr int T_B_HI = 2 * 128 * GP;
constexpr int T_B_LO = 3 * 128 * GP;
constexpr int STAGE  = 4 * 128 * GP;          // 40960
constexpr int GEMM_SMEM = 3 * STAGE;          // 122880

template <int EPI>
__global__ __launch_bounds__(256) void gemm_mma(
    const __nv_bfloat16* __restrict__ Ah, const __nv_bfloat16* __restrict__ Al,
    const __nv_bfloat16* __restrict__ Wh, const __nv_bfloat16* __restrict__ Wl,
    const float* __restrict__ bias,
    float* __restrict__ Yf,
    __nv_bfloat16* __restrict__ Yh, __nv_bfloat16* __restrict__ Yl)
{
    extern __shared__ __align__(16) char dsm[];
    const uint32_t sbase = smem_u32(dsm);
    const int tid = threadIdx.x;
    const int wid = tid >> 5, lane = tid & 31;
    const int b = blockIdx.x, nb = blockIdx.y, c = blockIdx.z;

    const size_t abase = ((size_t)b * CC + c) * SS * EE;
    const size_t wbase = (size_t)c * EE * EE + (size_t)nb * 128 * EE;

    auto issue = [&](int stg) {
        const int kb = stg * 32;
        const uint32_t sb = sbase + (stg % 3) * STAGE;
#pragma unroll
        for (int j = 0; j < 2; ++j) {
            const int t2 = tid + j * 256;
            const int row = t2 >> 2, ch = t2 & 3;
            const size_t goff = (size_t)row * EE + kb + ch * 8;
            const uint32_t so = row * GP + ch * 16;
            cp_async16(sb + T_A_HI + so, Ah + abase + goff);
            cp_async16(sb + T_A_LO + so, Al + abase + goff);
            cp_async16(sb + T_B_HI + so, Wh + wbase + goff);
            cp_async16(sb + T_B_LO + so, Wl + wbase + goff);
        }
    };
    issue(0); cp_commit();
    issue(1); cp_commit();
    issue(2); cp_commit();

    const int wm = wid & 3, wn = wid >> 2;
    const int g = lane >> 3, lr = lane & 7;

    float acc[2][8][4];
#pragma unroll
    for (int mi = 0; mi < 2; ++mi)
#pragma unroll
        for (int nj = 0; nj < 8; ++nj)
#pragma unroll
            for (int r = 0; r < 4; ++r) acc[mi][nj][r] = 0.f;

    for (int it = 0; it < 8; ++it) {
        cp_wait<2>();
        __syncthreads();
        const uint32_t st = sbase + (it % 3) * STAGE;

#pragma unroll
        for (int pass = 0; pass < 3; ++pass) {
            const uint32_t Ab = st + (pass == 2 ? T_A_LO : T_A_HI);
            const uint32_t Bb = st + (pass == 1 ? T_B_LO : T_B_HI);
#pragma unroll
            for (int k16 = 0; k16 < 2; ++k16) {
                uint32_t afr[2][4];
#pragma unroll
                for (int mi = 0; mi < 2; ++mi) {
                    const int row = wm * 32 + mi * 16 + ((g & 1) << 3) + lr;
                    const uint32_t addr = Ab + row * GP + (k16 * 2 + (g >> 1)) * 16;
                    ldsm_x4(afr[mi][0], afr[mi][1], afr[mi][2], afr[mi][3], addr);
                }
                uint32_t bfr[4][4];
#pragma unroll
                for (int ni = 0; ni < 4; ++ni) {
                    const int row = wn * 64 + ni * 16 + ((g >> 1) << 3) + lr;
                    const uint32_t addr = Bb + row * GP + (k16 * 2 + (g & 1)) * 16;
                    ldsm_x4(bfr[ni][0], bfr[ni][1], bfr[ni][2], bfr[ni][3], addr);
                }
#pragma unroll
                for (int mi = 0; mi < 2; ++mi)
#pragma unroll
                    for (int nj = 0; nj < 8; ++nj)
                        mma_bf16(acc[mi][nj], afr[mi],
                                 bfr[nj >> 1][(nj & 1) * 2],
                                 bfr[nj >> 1][(nj & 1) * 2 + 1]);
            }
        }
        __syncthreads();
        if (it + 3 < 8) issue(it + 3);
        cp_commit();
    }

#pragma unroll
    for (int mi = 0; mi < 2; ++mi) {
#pragma unroll
        for (int rr = 0; rr < 2; ++rr) {
            const int m = wm * 32 + mi * 16 + (lane >> 2) + rr * 8;
            const size_t yrow = abase + (size_t)m * EE + nb * 128;
#pragma unroll
            for (int nj = 0; nj < 8; ++nj) {
                const int col = wn * 64 + nj * 8 + (lane & 3) * 2;
                float v0 = acc[mi][nj][rr * 2 + 0];
                float v1 = acc[mi][nj][rr * 2 + 1];
                if constexpr (EPI == 0) {
                    *(float2*)(Yf + yrow + col) = make_float2(v0, v1);
                } else {
                    const float* bp = bias + (size_t)c * EE + nb * 128 + col;
                    v0 += bp[0];
                    v1 += bp[1];
                    if constexpr (EPI == 1) {
                        v0 = fmaxf(v0, 0.f);
                        v1 = fmaxf(v1, 0.f);
                        __nv_bfloat16 h0, l0, h1, l1;
                        split_bf16(v0, h0, l0);
                        split_bf16(v1, h1, l1);
                        *(__nv_bfloat162*)(Yh + yrow + col) = __halves2bfloat162(h0, h1);
                        *(__nv_bfloat162*)(Yl + yrow + col) = __halves2bfloat162(l0, l1);
                    } else {
                        *(float2*)(Yf + yrow + col) = make_float2(v0, v1);
                    }
                }
            }
        }
    }
}

// ---------------------------------------------------------------------------
// Spatial attention: one block per (b,s), all 8 heads. 768 threads.
// ---------------------------------------------------------------------------
constexpr int SA_PITCH = 257;
constexpr int SA_SMEM = (3 * CC * SA_PITCH + HH * CC * 25) * 4;

__global__ __launch_bounds__(768) void spatial_attn(
    const float* __restrict__ q, const float* __restrict__ k,
    const float* __restrict__ v, __nv_bfloat16* __restrict__ oh,
    __nv_bfloat16* __restrict__ ol)
{
    extern __shared__ float sa[];
    float* qs = sa;
    float* ks = qs + CC * SA_PITCH;
    float* vs = ks + CC * SA_PITCH;
    float* sc = vs + CC * SA_PITCH;

    const int s = blockIdx.x, b = blockIdx.y;
    const int t = threadIdx.x;
    const size_t gbase = ((size_t)b * CC * SS + s) * EE;
    const size_t cstride = (size_t)SS * EE;

#pragma unroll
    for (int i = 0; i < 8; ++i) {
        const int idx = t + i * 768;
        const int row = idx >> 8, e = idx & 255;
        const size_t g = gbase + row * cstride + e;
        qs[row * SA_PITCH + e] = q[g];
        ks[row * SA_PITCH + e] = k[g];
        vs[row * SA_PITCH + e] = v[g];
    }
    __syncthreads();

#pragma unroll
    for (int i = 0; i < 6; ++i) {
        const int idx = t + i * 768;
        const int h = idx / 576;
        const int r = idx - h * 576;
        const int ci = r / 24, di = r - (r / 24) * 24;
        const float* qr = qs + ci * SA_PITCH + h * 32;
        const float* kr = ks + di * SA_PITCH + h * 32;
        float sum = 0.f;
#pragma unroll
        for (int p = 0; p < 32; ++p) sum = fmaf(qr[p], kr[p], sum);
        sc[(h * CC + ci) * 25 + di] = sum * INV_SQRT_P;
    }
    __syncthreads();

    if (t < HH * CC) {
        float* row = sc + t * 25;
        float mx = -1e30f;
#pragma unroll
        for (int d = 0; d < CC; ++d) mx = fmaxf(mx, row[d]);
        float sm = 0.f;
#pragma unroll
        for (int d = 0; d < CC; ++d) { float e = __expf(row[d] - mx); row[d] = e; sm += e; }
        const float inv = 1.f / sm;
#pragma unroll
        for (int d = 0; d < CC; ++d) row[d] *= inv;
    }
    __syncthreads();

#pragma unroll
    for (int i = 0; i < 8; ++i) {
        const int idx = t + i * 768;
        const int h = idx / 768;
        const int r = idx - h * 768;
        const int cc = r >> 5, p = r & 31;
        const float* arow = sc + (h * CC + cc) * 25;
        float sum = 0.f;
#pragma unroll
        for (int d = 0; d < CC; ++d)
            sum = fmaf(arow[d], vs[d * SA_PITCH + h * 32 + p], sum);
        const size_t g = gbase + cc * cstride + h * 32 + p;
        __nv_bfloat16 hi, lo;
        split_bf16(sum, hi, lo);
        oh[g] = hi;
        ol[g] = lo;
    }
}

// ---------------------------------------------------------------------------
// Temporal attention (f32x2 packed FMA version). o -> bf16 pair.
// ---------------------------------------------------------------------------
constexpr int QK_PAD = 132, V_PAD = 36, SC_PAD = 129;
constexpr int TEMP_SMEM_BYTES = (2 * 32 * QK_PAD + SS * V_PAD + SS * SC_PAD) * 4;

__global__ __launch_bounds__(256) void temporal_attn(
    const float* __restrict__ q, const float* __restrict__ k,
    const float* __restrict__ v, __nv_bfloat16* __restrict__ oh,
    __nv_bfloat16* __restrict__ ol)
{
    extern __shared__ float smem[];
    float* qt = smem;                    // [32][QK_PAD]
    float* kt = qt + 32 * QK_PAD;        // [32][QK_PAD]
    float* vs = kt + 32 * QK_PAD;        // [128][V_PAD]
    float* sc = vs + SS * V_PAD;         // [128][SC_PAD]

    const int c = blockIdx.x, h = blockIdx.y, b = blockIdx.z;
    const int tid = threadIdx.x;
    const size_t base = (((size_t)b * CC + c) * SS) * EE + h * PP;

    for (int idx = tid; idx < SS * PP; idx += 256) {
        const int s = idx >> 5, p = idx & 31;
        const size_t g = base + (size_t)s * EE + p;
        qt[p * QK_PAD + s] = q[g];
        kt[p * QK_PAD + s] = k[g];
        vs[s * V_PAD + p]  = v[g];
    }
    __syncthreads();

    // ---- scores via f32x2 ----
    {
        const int tx = tid & 15, ty = tid >> 4;
        unsigned long long acc2[8][4];
#pragma unroll
        for (int i = 0; i < 8; ++i)
#pragma unroll
            for (int j = 0; j < 4; ++j) acc2[i][j] = 0ull;

#pragma unroll 4
        for (int p = 0; p < PP; ++p) {
            float4 a0 = *(const float4*)&qt[p * QK_PAD + ty * 8];
            float4 a1 = *(const float4*)&qt[p * QK_PAD + ty * 8 + 4];
            float ar[8] = {a0.x, a0.y, a0.z, a0.w, a1.x, a1.y, a1.z, a1.w};
            ulonglong2 bb01 = *(const ulonglong2*)&kt[p * QK_PAD + tx * 8];
            ulonglong2 bb23 = *(const ulonglong2*)&kt[p * QK_PAD + tx * 8 + 4];
            unsigned long long bb[4] = {bb01.x, bb01.y, bb23.x, bb23.y};
#pragma unroll
            for (int i = 0; i < 8; ++i) {
                const unsigned long long ap = pack2(ar[i]);
#pragma unroll
                for (int j = 0; j < 4; ++j) fma2(acc2[i][j], ap, bb[j]);
            }
        }
#pragma unroll
        for (int i = 0; i < 8; ++i)
#pragma unroll
            for (int j = 0; j < 4; ++j) {
                float2 u = unpack2(acc2[i][j]);
                sc[(ty * 8 + i) * SC_PAD + tx * 8 + j * 2 + 0] = u.x * INV_SQRT_P;
                sc[(ty * 8 + i) * SC_PAD + tx * 8 + j * 2 + 1] = u.y * INV_SQRT_P;
            }
    }
    __syncthreads();

    // ---- softmax: 2 threads per row ----
    {
        const int row = tid >> 1, half = tid & 1;
        float* r = sc + row * SC_PAD + half * 64;
        float mx = -1e30f;
#pragma unroll 8
        for (int t2 = 0; t2 < 64; ++t2) mx = fmaxf(mx, r[t2]);
        mx = fmaxf(mx, __shfl_xor_sync(0xffffffffu, mx, 1));
        float ssum = 0.f;
#pragma unroll 8
        for (int t2 = 0; t2 < 64; ++t2) {
            float e = __expf(r[t2] - mx);
            r[t2] = e;
            ssum += e;
        }
        ssum += __shfl_xor_sync(0xffffffffu, ssum, 1);
        const float inv = 1.f / ssum;
#pragma unroll 8
        for (int t2 = 0; t2 < 64; ++t2) r[t2] *= inv;
    }
    __syncthreads();

    // ---- AV via f32x2 ----
    {
        const int s0 = (tid >> 3) * 4;
        const int p0 = (tid & 7) * 4;
        unsigned long long acc2[4][2];
#pragma unroll
        for (int i = 0; i < 4; ++i) { acc2[i][0] = 0ull; acc2[i][1] = 0ull; }

#pragma unroll 4
        for (int t2 = 0; t2 < SS; ++t2) {
            ulonglong2 vv = *(const ulonglong2*)&vs[t2 * V_PAD + p0];
#pragma unroll
            for (int i = 0; i < 4; ++i) {
                const unsigned long long ap = pack2(sc[(s0 + i) * SC_PAD + t2]);
                fma2(acc2[i][0], ap, vv.x);
                fma2(acc2[i][1], ap, vv.y);
            }
        }
#pragma unroll
        for (int i = 0; i < 4; ++i) {
            float2 u0 = unpack2(acc2[i][0]);
            float2 u1 = unpack2(acc2[i][1]);
            float vv[4] = {u0.x, u0.y, u1.x, u1.y};
            const size_t g = base + (size_t)(s0 + i) * EE + p0;
            __nv_bfloat16 hh[4], ll[4];
#pragma unroll
            for (int j = 0; j < 4; ++j) split_bf16(vv[j], hh[j], ll[j]);
            *(__nv_bfloat162*)(oh + g)     = __halves2bfloat162(hh[0], hh[1]);
            *(__nv_bfloat162*)(oh + g + 2) = __halves2bfloat162(hh[2], hh[3]);
            *(__nv_bfloat162*)(ol + g)     = __halves2bfloat162(ll[0], ll[1]);
            *(__nv_bfloat162*)(ol + g + 2) = __halves2bfloat162(ll[2], ll[3]);
        }
    }
}

// ---------------------------------------------------------------------------
// LayerNorm kernels
// ---------------------------------------------------------------------------
__device__ __forceinline__ float blk_sum(float v, float* scratch)
{
    __syncthreads();
    const int lane = threadIdx.x & 31, w = threadIdx.x >> 5;
#pragma unroll
    for (int off = 16; off > 0; off >>= 1)
        v += __shfl_xor_sync(0xffffffffu, v, off);
    if (lane == 0) scratch[w] = v;
    __syncthreads();
    float tot = 0.f;
#pragma unroll
    for (int i = 0; i < 8; ++i) tot += scratch[i];
    return tot;
}

__global__ __launch_bounds__(256) void dual_ln(
    const float* __restrict__ x, const float* __restrict__ a,
    const float* __restrict__ b2, const float* __restrict__ g,
    const float* __restrict__ beta, float* __restrict__ out,
    __nv_bfloat16* __restrict__ oh, __nv_bfloat16* __restrict__ ol)
{
    __shared__ float scratch[8];
    const size_t off = (size_t)blockIdx.x * EE + threadIdx.x;
    const float xv = x[off];
    const float v1 = xv + a[off];
    const float v2 = xv + b2[off];

    const float s1 = blk_sum(v1, scratch);
    const float q1 = blk_sum(v1 * v1, scratch);
    const float s2 = blk_sum(v2, scratch);
    const float q2 = blk_sum(v2 * v2, scratch);

    const float invE = 1.f / (float)EE;
    const float m1 = s1 * invE, m2 = s2 * invE;
    const float r1 = rsqrtf(fmaxf(q1 * invE - m1 * m1, 0.f) + LN_EPS);
    const float r2 = rsqrtf(fmaxf(q2 * invE - m2 * m2, 0.f) + LN_EPS);
    const float gg = g[threadIdx.x], bt = beta[threadIdx.x];
    const float o = (v1 - m1) * r1 * gg + bt + (v2 - m2) * r2 * gg + bt;
    out[off] = o;
    __nv_bfloat16 hi, lo;
    split_bf16(o, hi, lo);
    oh[off] = hi;
    ol[off] = lo;
}

__global__ __launch_bounds__(256) void final_ln(
    const float* __restrict__ a, const float* __restrict__ f,
    const float* __restrict__ g, const float* __restrict__ beta,
    float* __restrict__ out)
{
    __shared__ float scratch[8];
    const size_t off = (size_t)blockIdx.x * EE + threadIdx.x;
    const float v = a[off] + f[off];
    const float s = blk_sum(v, scratch);
    const float q = blk_sum(v * v, scratch);
    const float invE = 1.f / (float)EE;
    const float m = s * invE;
    const float r = rsqrtf(fmaxf(q * invE - m * m, 0.f) + LN_EPS);
    out[off] = (v - m) * r * g[threadIdx.x] + beta[threadIdx.x];
}

// ---------------------------------------------------------------------------
// kernel_launch
// ---------------------------------------------------------------------------
extern "C" void kernel_launch(void* const* d_in, const int* in_sizes, int n_in,
                              void* d_out, int out_size)
{
    const float* x    = (const float*)d_in[0];
    const float* ln_g = (const float*)d_in[9];
    const float* ln_b = (const float*)d_in[10];
    const float* ff_b1 = (const float*)d_in[12];
    const float* ff_b2 = (const float*)d_in[14];
    float* out = (float*)d_out;

    float *qs, *ks, *vs, *qt, *kt, *vt, *spat, *temp, *attn, *ffo;
    __nv_bfloat16 *xh, *xl, *ah, *al, *hh, *hl, *wh, *wl;
    cudaGetSymbolAddress((void**)&qs,   g_qs);
    cudaGetSymbolAddress((void**)&ks,   g_ks);
    cudaGetSymbolAddress((void**)&vs,   g_vs);
    cudaGetSymbolAddress((void**)&qt,   g_qt);
    cudaGetSymbolAddress((void**)&kt,   g_kt);
    cudaGetSymbolAddress((void**)&vt,   g_vt);
    cudaGetSymbolAddress((void**)&spat, g_spat);
    cudaGetSymbolAddress((void**)&temp, g_temp);
    cudaGetSymbolAddress((void**)&attn, g_attn);
    cudaGetSymbolAddress((void**)&ffo,  g_ffo);
    cudaGetSymbolAddress((void**)&xh, g_xh);
    cudaGetSymbolAddress((void**)&xl, g_xl);
    cudaGetSymbolAddress((void**)&ah, g_ah);
    cudaGetSymbolAddress((void**)&al, g_al);
    cudaGetSymbolAddress((void**)&hh, g_hh);
    cudaGetSymbolAddress((void**)&hl, g_hl);
    cudaGetSymbolAddress((void**)&wh, g_wh);
    cudaGetSymbolAddress((void**)&wl, g_wl);

    cudaFuncSetAttribute(gemm_qkv6,   cudaFuncAttributeMaxDynamicSharedMemorySize, QKV_SMEM);
    cudaFuncSetAttribute(gemm_mma<0>, cudaFuncAttributeMaxDynamicSharedMemorySize, GEMM_SMEM);
    cudaFuncSetAttribute(gemm_mma<1>, cudaFuncAttributeMaxDynamicSharedMemorySize, GEMM_SMEM);
    cudaFuncSetAttribute(gemm_mma<2>, cudaFuncAttributeMaxDynamicSharedMemorySize, GEMM_SMEM);
    cudaFuncSetAttribute(spatial_attn, cudaFuncAttributeMaxDynamicSharedMemorySize, SA_SMEM);
    cudaFuncSetAttribute(temporal_attn, cudaFuncAttributeMaxDynamicSharedMemorySize, TEMP_SMEM_BYTES);

    // ---- conversions ----
    split_f32_kernel<<<NTOT / 4 / 256, 256>>>(x, xh, xl, NTOT / 4);
    WPtrs wp;
    wp.p[0] = (const float*)d_in[1];  // Wq_s
    wp.p[1] = (const float*)d_in[2];  // Wk_s
    wp.p[2] = (const float*)d_in[3];  // Wv_s
    wp.p[3] = (const float*)d_in[4];  // Wo_s
    wp.p[4] = (const float*)d_in[5];  // Wq_t
    wp.p[5] = (const float*)d_in[6];  // Wk_t
    wp.p[6] = (const float*)d_in[7];  // Wv_t
    wp.p[7] = (const float*)d_in[8];  // Wo_t
    wp.p[8] = (const float*)d_in[11]; // ff_w1
    wp.p[9] = (const float*)d_in[13]; // ff_w2
    convert_weights_t<<<dim3(64, CC, NW), 256>>>(wp, wh, wl);

    // ---- fused q/k/v projections (both branches) ----
    Out6 o6;
    o6.y[0] = qs; o6.y[1] = ks; o6.y[2] = vs;
    o6.y[3] = qt; o6.y[4] = kt; o6.y[5] = vt;
    gemm_qkv6<<<dim3(BB, 2, CC), 256, QKV_SMEM>>>(xh, xl, wh, wl, o6);

    // ---- attentions ----
    spatial_attn<<<dim3(SS, BB), 768, SA_SMEM>>>(qs, ks, vs, ah, al);
    temporal_attn<<<dim3(CC, HH, BB), 256, TEMP_SMEM_BYTES>>>(qt, kt, vt, hh, hl);

    // ---- output projections ----
    const dim3 ggrid(BB, 2, CC);
    gemm_mma<0><<<ggrid, 256, GEMM_SMEM>>>(ah, al, wh + 3*(size_t)WELEMS, wl + 3*(size_t)WELEMS, nullptr, spat, nullptr, nullptr);
    gemm_mma<0><<<ggrid, 256, GEMM_SMEM>>>(hh, hl, wh + 7*(size_t)WELEMS, wl + 7*(size_t)WELEMS, nullptr, temp, nullptr, nullptr);

    // ---- residual + dual LN (emits attn fp32 + bf16 pair) ----
    dual_ln<<<NROWS, 256>>>(x, spat, temp, ln_g, ln_b, attn, ah, al);

    // ---- per-joint FF + final LN ----
    gemm_mma<1><<<ggrid, 256, GEMM_SMEM>>>(ah, al, wh + 8*(size_t)WELEMS, wl + 8*(size_t)WELEMS, ff_b1, nullptr, hh, hl);
    gemm_mma<2><<<ggrid, 256, GEMM_SMEM>>>(hh, hl, wh + 9*(size_t)WELEMS, wl + 9*(size_t)WELEMS, ff_b2, ffo, nullptr, nullptr);
    final_ln<<<NROWS, 256>>>(attn, ffo, ln_g, ln_b, out);
}

// round 6
// speedup vs baseline: 2.8251x; 1.0808x over previous
#include <cuda_runtime.h>
#include <cuda_bf16.h>
#include <cstdint>
#include <cstddef>

// Problem dims
constexpr int BB = 16, CC = 24, SS = 128, EE = 256, HH = 8, PP = 32;
constexpr int NTOT  = BB * CC * SS * EE;     // 12,582,912
constexpr int NROWS = BB * CC * SS;          // 49,152
constexpr int WELEMS = CC * EE * EE;         // 1,572,864 per weight
constexpr int NW = 10;
constexpr float LN_EPS = 1e-6f;
constexpr float INV_SQRT_P = 0.17677669529663687f;

// ---------------------------------------------------------------------------
// Device scratch
// ---------------------------------------------------------------------------
__device__ float g_qs[NTOT], g_ks[NTOT], g_vs[NTOT];
__device__ float g_qt[NTOT], g_kt[NTOT], g_vt[NTOT];
__device__ float g_spat[NTOT], g_temp[NTOT], g_attn[NTOT], g_ffo[NTOT];
__device__ __align__(16) __nv_bfloat16 g_xh[NTOT], g_xl[NTOT];
__device__ __align__(16) __nv_bfloat16 g_ah[NTOT], g_al[NTOT];   // spatial-out / attn pair
__device__ __align__(16) __nv_bfloat16 g_hh[NTOT], g_hl[NTOT];   // temporal-out / ff hidden pair
__device__ __align__(16) __nv_bfloat16 g_wh[NW * WELEMS], g_wl[NW * WELEMS];

// ---------------------------------------------------------------------------
// PTX helpers (baseline ISA only)
// ---------------------------------------------------------------------------
__device__ __forceinline__ uint32_t smem_u32(const void* p) {
    uint32_t a;
    asm("{ .reg .u64 t; cvta.to.shared.u64 t, %1; cvt.u32.u64 %0, t; }"
        : "=r"(a) : "l"(p));
    return a;
}
__device__ __forceinline__ void cp_async16(uint32_t smem, const void* gmem) {
    asm volatile("cp.async.cg.shared.global [%0], [%1], 16;"
                 :: "r"(smem), "l"(gmem));
}
__device__ __forceinline__ void cp_commit() {
    asm volatile("cp.async.commit_group;");
}
template <int N>
__device__ __forceinline__ void cp_wait() {
    asm volatile("cp.async.wait_group %0;" :: "n"(N) : "memory");
}
__device__ __forceinline__ void ldsm_x4(uint32_t& r0, uint32_t& r1,
                                        uint32_t& r2, uint32_t& r3, uint32_t addr) {
    asm volatile("ldmatrix.sync.aligned.m8n8.x4.shared.b16 {%0,%1,%2,%3}, [%4];"
                 : "=r"(r0), "=r"(r1), "=r"(r2), "=r"(r3) : "r"(addr));
}
__device__ __forceinline__ void mma_bf16(float* d, const uint32_t* a,
                                         uint32_t b0, uint32_t b1) {
    asm volatile(
        "mma.sync.aligned.m16n8k16.row.col.f32.bf16.bf16.f32 "
        "{%0,%1,%2,%3}, {%4,%5,%6,%7}, {%8,%9}, {%0,%1,%2,%3};"
        : "+f"(d[0]), "+f"(d[1]), "+f"(d[2]), "+f"(d[3])
        : "r"(a[0]), "r"(a[1]), "r"(a[2]), "r"(a[3]), "r"(b0), "r"(b1));
}
// packed f32x2
__device__ __forceinline__ unsigned long long pack2(float v) {
    unsigned long long r;
    asm("mov.b64 %0, {%1, %1};" : "=l"(r) : "f"(v));
    return r;
}
__device__ __forceinline__ void fma2(unsigned long long& d,
                                     unsigned long long a, unsigned long long b) {
    asm("fma.rn.f32x2 %0, %1, %2, %0;" : "+l"(d) : "l"(a), "l"(b));
}
__device__ __forceinline__ float2 unpack2(unsigned long long v) {
    float2 f;
    asm("mov.b64 {%0, %1}, %2;" : "=f"(f.x), "=f"(f.y) : "l"(v));
    return f;
}

// ---------------------------------------------------------------------------
// bf16 hi/lo split helpers
// ---------------------------------------------------------------------------
__device__ __forceinline__ void split_bf16(float x, __nv_bfloat16& h, __nv_bfloat16& l) {
    h = __float2bfloat16_rn(x);
    l = __float2bfloat16_rn(x - __bfloat162float(h));
}

__global__ __launch_bounds__(256) void split_f32_kernel(
    const float* __restrict__ src, __nv_bfloat16* __restrict__ hi,
    __nv_bfloat16* __restrict__ lo, int n4)
{
    int i = blockIdx.x * 256 + threadIdx.x;
    if (i >= n4) return;
    float4 v = ((const float4*)src)[i];
    float vv[4] = {v.x, v.y, v.z, v.w};
    __nv_bfloat16 h[4], l[4];
#pragma unroll
    for (int j = 0; j < 4; ++j) split_bf16(vv[j], h[j], l[j]);
    __nv_bfloat162* hp = (__nv_bfloat162*)hi;
    __nv_bfloat162* lp = (__nv_bfloat162*)lo;
    hp[i * 2 + 0] = __halves2bfloat162(h[0], h[1]);
    hp[i * 2 + 1] = __halves2bfloat162(h[2], h[3]);
    lp[i * 2 + 0] = __halves2bfloat162(l[0], l[1]);
    lp[i * 2 + 1] = __halves2bfloat162(l[2], l[3]);
}

// ---------------------------------------------------------------------------
// Weight conversion, coalesced: 32x32 (e,f) tiles via smem transpose.
// ---------------------------------------------------------------------------
struct WPtrs { const float* p[NW]; };

__global__ __launch_bounds__(256) void convert_weights_t(
    WPtrs wp, __nv_bfloat16* __restrict__ wh, __nv_bfloat16* __restrict__ wl)
{
    __shared__ float tile[32][33];
    const int w = blockIdx.z, c = blockIdx.y;
    const int eb = blockIdx.x & 7, fb = blockIdx.x >> 3;
    const int mode = (w == 3 || w >= 7) ? 0 : (w == 0 ? 1 : (w <= 2 ? 2 : 3));
    const int t = threadIdx.x;
    const int col = t & 31, r0 = t >> 5;
    const float* W = wp.p[w];

#pragma unroll
    for (int i = 0; i < 4; ++i) {
        const int row = r0 + i * 8;
        float v;
        if (mode == 0) {
            const int e = eb * 32 + row, f = fb * 32 + col;
            v = W[((size_t)c * EE + e) * EE + f];
        } else if (mode == 1) {
            const int f = fb * 32 + row, e = eb * 32 + col;
            const int h = fb, p = f & 31;
            v = W[(((size_t)h * CC + c) * PP + p) * EE + e];
        } else if (mode == 2) {
            const int e = eb * 32 + row, p = col, h = fb;
            v = W[((size_t)h * EE + e) * PP + p];
        } else {
            const int e = eb * 32 + row, p = col, h = fb;
            v = W[(((size_t)h * CC + c) * EE + e) * PP + p];
        }
        tile[row][col] = v;
    }
    __syncthreads();

#pragma unroll
    for (int i = 0; i < 4; ++i) {
        const int fr = r0 + i * 8;
        const int f = fb * 32 + fr;
        const int e = eb * 32 + col;
        const float v = (mode == 1) ? tile[fr][col] : tile[col][fr];
        __nv_bfloat16 hi, lo;
        split_bf16(v, hi, lo);
        const size_t o = (size_t)w * WELEMS + ((size_t)c << 16) + (size_t)f * EE + e;
        wh[o] = hi;
        wl[o] = lo;
    }
}

// ---------------------------------------------------------------------------
// Fused QKVx6 GEMM (A resident, 48 streamed B stages, triple-buffered)
// ---------------------------------------------------------------------------
constexpr int AP = 528;
constexpr int QA_HI = 0;
constexpr int QA_LO = 128 * AP;
constexpr int QB0   = 2 * 128 * AP;
constexpr int QB_STG = 20480;
constexpr int QKV_SMEM = QB0 + 3 * QB_STG;

constexpr int GP = 80;

struct Out6 { float* y[6]; };

__global__ __launch_bounds__(256) void gemm_qkv6(
    const __nv_bfloat16* __restrict__ xh, const __nv_bfloat16* __restrict__ xl,
    const __nv_bfloat16* __restrict__ whB, const __nv_bfloat16* __restrict__ wlB,
    Out6 outs)
{
    extern __shared__ __align__(16) char dsm[];
    const uint32_t sbase = smem_u32(dsm);
    const int tid = threadIdx.x;
    const int wid = tid >> 5, lane = tid & 31;
    const int b = blockIdx.x, nb = blockIdx.y, c = blockIdx.z;

    const size_t abase = ((size_t)b * CC + c) * SS * EE;

#pragma unroll
    for (int i = 0; i < 16; ++i) {
        const int t2 = tid + i * 256;
        const int row = t2 >> 5, ch = t2 & 31;
        const size_t goff = (size_t)row * EE + ch * 8;
        const uint32_t so = row * AP + ch * 16;
        cp_async16(sbase + QA_HI + so, xh + abase + goff);
        cp_async16(sbase + QA_LO + so, xl + abase + goff);
    }
    cp_commit();

    auto issueB = [&](int stage) {
        const int w = stage >> 3, kb = (stage & 7) * 32;
        const int wg = w + (w >= 3);
        const __nv_bfloat16* Wh = whB + (size_t)wg * WELEMS + ((size_t)c << 16)
                                + (size_t)nb * 128 * EE;
        const __nv_bfloat16* Wl = wlB + (size_t)wg * WELEMS + ((size_t)c << 16)
                                + (size_t)nb * 128 * EE;
        const uint32_t sb = sbase + QB0 + (stage % 3) * QB_STG;
#pragma unroll
        for (int j = 0; j < 2; ++j) {
            const int t2 = tid + j * 256;
            const int row = t2 >> 2, ch = t2 & 3;
            const size_t goff = (size_t)row * EE + kb + ch * 8;
            const uint32_t so = row * GP + ch * 16;
            cp_async16(sb + so, Wh + goff);
            cp_async16(sb + 10240 + so, Wl + goff);
        }
    };
    issueB(0); cp_commit();
    issueB(1); cp_commit();
    issueB(2); cp_commit();

    const int wm = wid & 3, wn = wid >> 2;
    const int g = lane >> 3, lr = lane & 7;

    for (int w = 0; w < 6; ++w) {
        float acc[2][8][4];
#pragma unroll
        for (int mi = 0; mi < 2; ++mi)
#pragma unroll
            for (int nj = 0; nj < 8; ++nj)
#pragma unroll
                for (int r = 0; r < 4; ++r) acc[mi][nj][r] = 0.f;

        for (int it = 0; it < 8; ++it) {
            const int stage = w * 8 + it;
            cp_wait<2>();
            __syncthreads();
            const uint32_t Bst = sbase + QB0 + (stage % 3) * QB_STG;

#pragma unroll
            for (int pass = 0; pass < 3; ++pass) {
                const uint32_t Ab = sbase + (pass == 2 ? QA_LO : QA_HI);
                const uint32_t Bb = Bst + (pass == 1 ? 10240 : 0);
#pragma unroll
                for (int k16 = 0; k16 < 2; ++k16) {
                    uint32_t afr[2][4];
#pragma unroll
                    for (int mi = 0; mi < 2; ++mi) {
                        const int row = wm * 32 + mi * 16 + ((g & 1) << 3) + lr;
                        const uint32_t addr =
                            Ab + row * AP + (it * 4 + k16 * 2 + (g >> 1)) * 16;
                        ldsm_x4(afr[mi][0], afr[mi][1], afr[mi][2], afr[mi][3], addr);
                    }
                    uint32_t bfr[4][4];
#pragma unroll
                    for (int ni = 0; ni < 4; ++ni) {
                        const int row = wn * 64 + ni * 16 + ((g >> 1) << 3) + lr;
                        const uint32_t addr = Bb + row * GP + (k16 * 2 + (g & 1)) * 16;
                        ldsm_x4(bfr[ni][0], bfr[ni][1], bfr[ni][2], bfr[ni][3], addr);
                    }
#pragma unroll
                    for (int mi = 0; mi < 2; ++mi)
#pragma unroll
                        for (int nj = 0; nj < 8; ++nj)
                            mma_bf16(acc[mi][nj], afr[mi],
                                     bfr[nj >> 1][(nj & 1) * 2],
                                     bfr[nj >> 1][(nj & 1) * 2 + 1]);
                }
            }
            __syncthreads();
            if (stage + 3 < 48) issueB(stage + 3);
            cp_commit();
        }

        float* Yf = outs.y[w];
#pragma unroll
        for (int mi = 0; mi < 2; ++mi)
#pragma unroll
            for (int rr = 0; rr < 2; ++rr) {
                const int m = wm * 32 + mi * 16 + (lane >> 2) + rr * 8;
                const size_t yrow = abase + (size_t)m * EE + nb * 128;
#pragma unroll
                for (int nj = 0; nj < 8; ++nj) {
                    const int colo = wn * 64 + nj * 8 + (lane & 3) * 2;
                    *(float2*)(Yf + yrow + colo) =
                        make_float2(acc[mi][nj][rr * 2 + 0], acc[mi][nj][rr * 2 + 1]);
                }
            }
    }
}

// ---------------------------------------------------------------------------
// Generic HMMA GEMM body: 128x128, 2-stage cp.async, 2 CTAs/SM.
// ---------------------------------------------------------------------------
constexpr int T_A_HI = 0;
constexpr int T_A_LO = 128 * GP;
constexpr int T_B_HI = 2 * 128 * GP;
constexpr int T_B_LO = 3 * 128 * GP;
constexpr int STAGE  = 4 * 128 * GP;          // 40960
constexpr int GEMM_SMEM = 2 * STAGE;          // 81920

template <int EPI>
__device__ __forceinline__ void gemm_body(
    const __nv_bfloat16* __restrict__ Ah, const __nv_bfloat16* __restrict__ Al,
    const __nv_bfloat16* __restrict__ Wh, const __nv_bfloat16* __restrict__ Wl,
    const float* __restrict__ bias,
    float* __restrict__ Yf,
    __nv_bfloat16* __restrict__ Yh, __nv_bfloat16* __restrict__ Yl,
    int b, int nb, int c, uint32_t sbase)
{
    const int tid = threadIdx.x;
    const int wid = tid >> 5, lane = tid & 31;

    const size_t abase = ((size_t)b * CC + c) * SS * EE;
    const size_t wbase = (size_t)c * EE * EE + (size_t)nb * 128 * EE;

    auto issue = [&](int stg) {
        const int kb = stg * 32;
        const uint32_t sb = sbase + (stg & 1) * STAGE;
#pragma unroll
        for (int j = 0; j < 2; ++j) {
            const int t2 = tid + j * 256;
            const int row = t2 >> 2, ch = t2 & 3;
            const size_t goff = (size_t)row * EE + kb + ch * 8;
            const uint32_t so = row * GP + ch * 16;
            cp_async16(sb + T_A_HI + so, Ah + abase + goff);
            cp_async16(sb + T_A_LO + so, Al + abase + goff);
            cp_async16(sb + T_B_HI + so, Wh + wbase + goff);
            cp_async16(sb + T_B_LO + so, Wl + wbase + goff);
        }
    };
    issue(0); cp_commit();
    issue(1); cp_commit();

    const int wm = wid & 3, wn = wid >> 2;
    const int g = lane >> 3, lr = lane & 7;

    float acc[2][8][4];
#pragma unroll
    for (int mi = 0; mi < 2; ++mi)
#pragma unroll
        for (int nj = 0; nj < 8; ++nj)
#pragma unroll
            for (int r = 0; r < 4; ++r) acc[mi][nj][r] = 0.f;

    for (int it = 0; it < 8; ++it) {
        cp_wait<1>();
        __syncthreads();
        const uint32_t st = sbase + (it & 1) * STAGE;

#pragma unroll
        for (int pass = 0; pass < 3; ++pass) {
            const uint32_t Ab = st + (pass == 2 ? T_A_LO : T_A_HI);
            const uint32_t Bb = st + (pass == 1 ? T_B_LO : T_B_HI);
#pragma unroll
            for (int k16 = 0; k16 < 2; ++k16) {
                uint32_t afr[2][4];
#pragma unroll
                for (int mi = 0; mi < 2; ++mi) {
                    const int row = wm * 32 + mi * 16 + ((g & 1) << 3) + lr;
                    const uint32_t addr = Ab + row * GP + (k16 * 2 + (g >> 1)) * 16;
                    ldsm_x4(afr[mi][0], afr[mi][1], afr[mi][2], afr[mi][3], addr);
                }
                uint32_t bfr[4][4];
#pragma unroll
                for (int ni = 0; ni < 4; ++ni) {
                    const int row = wn * 64 + ni * 16 + ((g >> 1) << 3) + lr;
                    const uint32_t addr = Bb + row * GP + (k16 * 2 + (g & 1)) * 16;
                    ldsm_x4(bfr[ni][0], bfr[ni][1], bfr[ni][2], bfr[ni][3], addr);
                }
#pragma unroll
                for (int mi = 0; mi < 2; ++mi)
#pragma unroll
                    for (int nj = 0; nj < 8; ++nj)
                        mma_bf16(acc[mi][nj], afr[mi],
                                 bfr[nj >> 1][(nj & 1) * 2],
                                 bfr[nj >> 1][(nj & 1) * 2 + 1]);
            }
        }
        __syncthreads();
        if (it + 2 < 8) issue(it + 2);
        cp_commit();
    }

#pragma unroll
    for (int mi = 0; mi < 2; ++mi) {
#pragma unroll
        for (int rr = 0; rr < 2; ++rr) {
            const int m = wm * 32 + mi * 16 + (lane >> 2) + rr * 8;
            const size_t yrow = abase + (size_t)m * EE + nb * 128;
#pragma unroll
            for (int nj = 0; nj < 8; ++nj) {
                const int col = wn * 64 + nj * 8 + (lane & 3) * 2;
                float v0 = acc[mi][nj][rr * 2 + 0];
                float v1 = acc[mi][nj][rr * 2 + 1];
                if constexpr (EPI == 0) {
                    *(float2*)(Yf + yrow + col) = make_float2(v0, v1);
                } else {
                    const float* bp = bias + (size_t)c * EE + nb * 128 + col;
                    v0 += bp[0];
                    v1 += bp[1];
                    if constexpr (EPI == 1) {
                        v0 = fmaxf(v0, 0.f);
                        v1 = fmaxf(v1, 0.f);
                        __nv_bfloat16 h0, l0, h1, l1;
                        split_bf16(v0, h0, l0);
                        split_bf16(v1, h1, l1);
                        *(__nv_bfloat162*)(Yh + yrow + col) = __halves2bfloat162(h0, h1);
                        *(__nv_bfloat162*)(Yl + yrow + col) = __halves2bfloat162(l0, l1);
                    } else {
                        *(float2*)(Yf + yrow + col) = make_float2(v0, v1);
                    }
                }
            }
        }
    }
}

template <int EPI>
__global__ __launch_bounds__(256, 2) void gemm_mma(
    const __nv_bfloat16* __restrict__ Ah, const __nv_bfloat16* __restrict__ Al,
    const __nv_bfloat16* __restrict__ Wh, const __nv_bfloat16* __restrict__ Wl,
    const float* __restrict__ bias,
    float* __restrict__ Yf,
    __nv_bfloat16* __restrict__ Yh, __nv_bfloat16* __restrict__ Yl)
{
    extern __shared__ __align__(16) char dsm[];
    gemm_body<EPI>(Ah, Al, Wh, Wl, bias, Yf, Yh, Yl,
                   blockIdx.x, blockIdx.y, blockIdx.z, smem_u32(dsm));
}

// Merged dual output-projection launch (spat and temp branches).
__global__ __launch_bounds__(256, 2) void gemm_wo_pair(
    const __nv_bfloat16* __restrict__ Ah0, const __nv_bfloat16* __restrict__ Al0,
    const __nv_bfloat16* __restrict__ Wh0, const __nv_bfloat16* __restrict__ Wl0,
    float* __restrict__ Y0,
    const __nv_bfloat16* __restrict__ Ah1, const __nv_bfloat16* __restrict__ Al1,
    const __nv_bfloat16* __restrict__ Wh1, const __nv_bfloat16* __restrict__ Wl1,
    float* __restrict__ Y1)
{
    extern __shared__ __align__(16) char dsm[];
    const int zz = blockIdx.z;
    const int br = zz >= CC;
    const int c = br ? zz - CC : zz;
    gemm_body<0>(br ? Ah1 : Ah0, br ? Al1 : Al0,
                 br ? Wh1 : Wh0, br ? Wl1 : Wl0,
                 nullptr, br ? Y1 : Y0, nullptr, nullptr,
                 blockIdx.x, blockIdx.y, c, smem_u32(dsm));
}

// ---------------------------------------------------------------------------
// Spatial attention v3: one block per (b,s), all 8 heads, 768 threads.
// Register-tiled score (2ci x 3di) and AV (p-quad) phases; pitch 260
// (float4-aligned, bank-verified conflict-free).
// ---------------------------------------------------------------------------
constexpr int SA_P = 260;
constexpr int SA_SMEM = (3 * CC * SA_P + HH * CC * 25) * 4;  // 94,080 B

__global__ __launch_bounds__(768) void spatial_attn(
    const float* __restrict__ q, const float* __restrict__ k,
    const float* __restrict__ v, __nv_bfloat16* __restrict__ oh,
    __nv_bfloat16* __restrict__ ol)
{
    extern __shared__ float sa[];
    float* qs = sa;
    float* ks = qs + CC * SA_P;
    float* vs = ks + CC * SA_P;
    float* sc = vs + CC * SA_P;   // [192][25]

    const int s = blockIdx.x, b = blockIdx.y;
    const int t = threadIdx.x;
    const size_t gbase = ((size_t)b * CC * SS + s) * EE;
    const size_t cstride = (size_t)SS * EE;

    // ---- loads: float4, 24 rows x 64 float4-chunks per tensor ----
#pragma unroll
    for (int i = 0; i < 2; ++i) {
        const int idx = t + i * 768;          // 0..1535
        const int row = idx >> 6, e4 = idx & 63;
        const size_t g = gbase + row * cstride + e4 * 4;
        const int so = row * SA_P + e4 * 4;
        *(float4*)(qs + so) = *(const float4*)(q + g);
        *(float4*)(ks + so) = *(const float4*)(k + g);
        *(float4*)(vs + so) = *(const float4*)(v + g);
    }
    __syncthreads();

    // ---- scores: per h, 96 threads = 12 ci-groups(2) x 8 di-groups(3) ----
    {
        const int h = t / 96;
        const int r = t - h * 96;
        const int cig = r >> 3, dig = r & 7;
        const int ci0 = cig * 2, di0 = dig * 3;
        const float* qb = qs + ci0 * SA_P + h * 32;
        const float* kb = ks + di0 * SA_P + h * 32;
        float a00 = 0.f, a01 = 0.f, a02 = 0.f;
        float a10 = 0.f, a11 = 0.f, a12 = 0.f;
#pragma unroll
        for (int p = 0; p < 32; ++p) {
            const float q0 = qb[p], q1 = qb[SA_P + p];
            const float k0 = kb[p], k1 = kb[SA_P + p], k2 = kb[2 * SA_P + p];
            a00 = fmaf(q0, k0, a00); a01 = fmaf(q0, k1, a01); a02 = fmaf(q0, k2, a02);
            a10 = fmaf(q1, k0, a10); a11 = fmaf(q1, k1, a11); a12 = fmaf(q1, k2, a12);
        }
        float* sr0 = sc + (h * CC + ci0) * 25 + di0;
        float* sr1 = sr0 + 25;
        sr0[0] = a00 * INV_SQRT_P; sr0[1] = a01 * INV_SQRT_P; sr0[2] = a02 * INV_SQRT_P;
        sr1[0] = a10 * INV_SQRT_P; sr1[1] = a11 * INV_SQRT_P; sr1[2] = a12 * INV_SQRT_P;
    }
    __syncthreads();

    // ---- softmax over di (192 rows) ----
    if (t < HH * CC) {
        float* row = sc + t * 25;
        float mx = -1e30f;
#pragma unroll
        for (int d = 0; d < CC; ++d) mx = fmaxf(mx, row[d]);
        float sm = 0.f;
#pragma unroll
        for (int d = 0; d < CC; ++d) { float e = __expf(row[d] - mx); row[d] = e; sm += e; }
        const float inv = 1.f / sm;
#pragma unroll
        for (int d = 0; d < CC; ++d) row[d] *= inv;
    }
    __syncthreads();

    // ---- AV: thread -> 2 items of (h, cc, p-quad) ----
#pragma unroll
    for (int i = 0; i < 2; ++i) {
        const int item = t + i * 768;         // 0..1535
        const int h = item / 192;
        const int rr = item - h * 192;
        const int cc = rr >> 3, p4 = (rr & 7) * 4;
        const float* arow = sc + (h * CC + cc) * 25;
        const float* vb = vs + h * 32 + p4;
        float s0 = 0.f, s1 = 0.f, s2 = 0.f, s3 = 0.f;
#pragma unroll
        for (int d = 0; d < CC; ++d) {
            const float a = arow[d];
            const float4 vv = *(const float4*)(vb + d * SA_P);
            s0 = fmaf(a, vv.x, s0); s1 = fmaf(a, vv.y, s1);
            s2 = fmaf(a, vv.z, s2); s3 = fmaf(a, vv.w, s3);
        }
        const size_t g = gbase + cc * cstride + h * 32 + p4;
        __nv_bfloat16 h0, l0, h1, l1, h2, l2, h3, l3;
        split_bf16(s0, h0, l0); split_bf16(s1, h1, l1);
        split_bf16(s2, h2, l2); split_bf16(s3, h3, l3);
        *(__nv_bfloat162*)(oh + g)     = __halves2bfloat162(h0, h1);
        *(__nv_bfloat162*)(oh + g + 2) = __halves2bfloat162(h2, h3);
        *(__nv_bfloat162*)(ol + g)     = __halves2bfloat162(l0, l1);
        *(__nv_bfloat162*)(ol + g + 2) = __halves2bfloat162(l2, l3);
    }
}

// ---------------------------------------------------------------------------
// Temporal attention (f32x2 packed FMA). o -> bf16 pair.
// ---------------------------------------------------------------------------
constexpr int QK_PAD = 132, V_PAD = 36, SC_PAD = 129;
constexpr int TEMP_SMEM_BYTES = (2 * 32 * QK_PAD + SS * V_PAD + SS * SC_PAD) * 4;

__global__ __launch_bounds__(256) void temporal_attn(
    const float* __restrict__ q, const float* __restrict__ k,
    const float* __restrict__ v, __nv_bfloat16* __restrict__ oh,
    __nv_bfloat16* __restrict__ ol)
{
    extern __shared__ float smem[];
    float* qt = smem;
    float* kt = qt + 32 * QK_PAD;
    float* vs = kt + 32 * QK_PAD;
    float* sc = vs + SS * V_PAD;

    const int c = blockIdx.x, h = blockIdx.y, b = blockIdx.z;
    const int tid = threadIdx.x;
    const size_t base = (((size_t)b * CC + c) * SS) * EE + h * PP;

    for (int idx = tid; idx < SS * PP; idx += 256) {
        const int s = idx >> 5, p = idx & 31;
        const size_t g = base + (size_t)s * EE + p;
        qt[p * QK_PAD + s] = q[g];
        kt[p * QK_PAD + s] = k[g];
        vs[s * V_PAD + p]  = v[g];
    }
    __syncthreads();

    {
        const int tx = tid & 15, ty = tid >> 4;
        unsigned long long acc2[8][4];
#pragma unroll
        for (int i = 0; i < 8; ++i)
#pragma unroll
            for (int j = 0; j < 4; ++j) acc2[i][j] = 0ull;

#pragma unroll 4
        for (int p = 0; p < PP; ++p) {
            float4 a0 = *(const float4*)&qt[p * QK_PAD + ty * 8];
            float4 a1 = *(const float4*)&qt[p * QK_PAD + ty * 8 + 4];
            float ar[8] = {a0.x, a0.y, a0.z, a0.w, a1.x, a1.y, a1.z, a1.w};
            ulonglong2 bb01 = *(const ulonglong2*)&kt[p * QK_PAD + tx * 8];
            ulonglong2 bb23 = *(const ulonglong2*)&kt[p * QK_PAD + tx * 8 + 4];
            unsigned long long bb[4] = {bb01.x, bb01.y, bb23.x, bb23.y};
#pragma unroll
            for (int i = 0; i < 8; ++i) {
                const unsigned long long ap = pack2(ar[i]);
#pragma unroll
                for (int j = 0; j < 4; ++j) fma2(acc2[i][j], ap, bb[j]);
            }
        }
#pragma unroll
        for (int i = 0; i < 8; ++i)
#pragma unroll
            for (int j = 0; j < 4; ++j) {
                float2 u = unpack2(acc2[i][j]);
                sc[(ty * 8 + i) * SC_PAD + tx * 8 + j * 2 + 0] = u.x * INV_SQRT_P;
                sc[(ty * 8 + i) * SC_PAD + tx * 8 + j * 2 + 1] = u.y * INV_SQRT_P;
            }
    }
    __syncthreads();

    {
        const int row = tid >> 1, half = tid & 1;
        float* r = sc + row * SC_PAD + half * 64;
        float mx = -1e30f;
#pragma unroll 8
        for (int t2 = 0; t2 < 64; ++t2) mx = fmaxf(mx, r[t2]);
        mx = fmaxf(mx, __shfl_xor_sync(0xffffffffu, mx, 1));
        float ssum = 0.f;
#pragma unroll 8
        for (int t2 = 0; t2 < 64; ++t2) {
            float e = __expf(r[t2] - mx);
            r[t2] = e;
            ssum += e;
        }
        ssum += __shfl_xor_sync(0xffffffffu, ssum, 1);
        const float inv = 1.f / ssum;
#pragma unroll 8
        for (int t2 = 0; t2 < 64; ++t2) r[t2] *= inv;
    }
    __syncthreads();

    {
        const int s0 = (tid >> 3) * 4;
        const int p0 = (tid & 7) * 4;
        unsigned long long acc2[4][2];
#pragma unroll
        for (int i = 0; i < 4; ++i) { acc2[i][0] = 0ull; acc2[i][1] = 0ull; }

#pragma unroll 4
        for (int t2 = 0; t2 < SS; ++t2) {
            ulonglong2 vv = *(const ulonglong2*)&vs[t2 * V_PAD + p0];
#pragma unroll
            for (int i = 0; i < 4; ++i) {
                const unsigned long long ap = pack2(sc[(s0 + i) * SC_PAD + t2]);
                fma2(acc2[i][0], ap, vv.x);
                fma2(acc2[i][1], ap, vv.y);
            }
        }
#pragma unroll
        for (int i = 0; i < 4; ++i) {
            float2 u0 = unpack2(acc2[i][0]);
            float2 u1 = unpack2(acc2[i][1]);
            float vv[4] = {u0.x, u0.y, u1.x, u1.y};
            const size_t g = base + (size_t)(s0 + i) * EE + p0;
            __nv_bfloat16 hh[4], ll[4];
#pragma unroll
            for (int j = 0; j < 4; ++j) split_bf16(vv[j], hh[j], ll[j]);
            *(__nv_bfloat162*)(oh + g)     = __halves2bfloat162(hh[0], hh[1]);
            *(__nv_bfloat162*)(oh + g + 2) = __halves2bfloat162(hh[2], hh[3]);
            *(__nv_bfloat162*)(ol + g)     = __halves2bfloat162(ll[0], ll[1]);
            *(__nv_bfloat162*)(ol + g + 2) = __halves2bfloat162(ll[2], ll[3]);
        }
    }
}

// ---------------------------------------------------------------------------
// LayerNorm kernels
// ---------------------------------------------------------------------------
__device__ __forceinline__ float blk_sum(float v, float* scratch)
{
    __syncthreads();
    const int lane = threadIdx.x & 31, w = threadIdx.x >> 5;
#pragma unroll
    for (int off = 16; off > 0; off >>= 1)
        v += __shfl_xor_sync(0xffffffffu, v, off);
    if (lane == 0) scratch[w] = v;
    __syncthreads();
    float tot = 0.f;
#pragma unroll
    for (int i = 0; i < 8; ++i) tot += scratch[i];
    return tot;
}

__global__ __launch_bounds__(256) void dual_ln(
    const float* __restrict__ x, const float* __restrict__ a,
    const float* __restrict__ b2, const float* __restrict__ g,
    const float* __restrict__ beta, float* __restrict__ out,
    __nv_bfloat16* __restrict__ oh, __nv_bfloat16* __restrict__ ol)
{
    __shared__ float scratch[8];
    const size_t off = (size_t)blockIdx.x * EE + threadIdx.x;
    const float xv = x[off];
    const float v1 = xv + a[off];
    const float v2 = xv + b2[off];

    const float s1 = blk_sum(v1, scratch);
    const float q1 = blk_sum(v1 * v1, scratch);
    const float s2 = blk_sum(v2, scratch);
    const float q2 = blk_sum(v2 * v2, scratch);

    const float invE = 1.f / (float)EE;
    const float m1 = s1 * invE, m2 = s2 * invE;
    const float r1 = rsqrtf(fmaxf(q1 * invE - m1 * m1, 0.f) + LN_EPS);
    const float r2 = rsqrtf(fmaxf(q2 * invE - m2 * m2, 0.f) + LN_EPS);
    const float gg = g[threadIdx.x], bt = beta[threadIdx.x];
    const float o = (v1 - m1) * r1 * gg + bt + (v2 - m2) * r2 * gg + bt;
    out[off] = o;
    __nv_bfloat16 hi, lo;
    split_bf16(o, hi, lo);
    oh[off] = hi;
    ol[off] = lo;
}

__global__ __launch_bounds__(256) void final_ln(
    const float* __restrict__ a, const float* __restrict__ f,
    const float* __restrict__ g, const float* __restrict__ beta,
    float* __restrict__ out)
{
    __shared__ float scratch[8];
    const size_t off = (size_t)blockIdx.x * EE + threadIdx.x;
    const float v = a[off] + f[off];
    const float s = blk_sum(v, scratch);
    const float q = blk_sum(v * v, scratch);
    const float invE = 1.f / (float)EE;
    const float m = s * invE;
    const float r = rsqrtf(fmaxf(q * invE - m * m, 0.f) + LN_EPS);
    out[off] = (v - m) * r * g[threadIdx.x] + beta[threadIdx.x];
}

// ---------------------------------------------------------------------------
// kernel_launch
// ---------------------------------------------------------------------------
extern "C" void kernel_launch(void* const* d_in, const int* in_sizes, int n_in,
                              void* d_out, int out_size)
{
    const float* x    = (const float*)d_in[0];
    const float* ln_g = (const float*)d_in[9];
    const float* ln_b = (const float*)d_in[10];
    const float* ff_b1 = (const float*)d_in[12];
    const float* ff_b2 = (const float*)d_in[14];
    float* out = (float*)d_out;

    float *qs, *ks, *vs, *qt, *kt, *vt, *spat, *temp, *attn, *ffo;
    __nv_bfloat16 *xh, *xl, *ah, *al, *hh, *hl, *wh, *wl;
    cudaGetSymbolAddress((void**)&qs,   g_qs);
    cudaGetSymbolAddress((void**)&ks,   g_ks);
    cudaGetSymbolAddress((void**)&vs,   g_vs);
    cudaGetSymbolAddress((void**)&qt,   g_qt);
    cudaGetSymbolAddress((void**)&kt,   g_kt);
    cudaGetSymbolAddress((void**)&vt,   g_vt);
    cudaGetSymbolAddress((void**)&spat, g_spat);
    cudaGetSymbolAddress((void**)&temp, g_temp);
    cudaGetSymbolAddress((void**)&attn, g_attn);
    cudaGetSymbolAddress((void**)&ffo,  g_ffo);
    cudaGetSymbolAddress((void**)&xh, g_xh);
    cudaGetSymbolAddress((void**)&xl, g_xl);
    cudaGetSymbolAddress((void**)&ah, g_ah);
    cudaGetSymbolAddress((void**)&al, g_al);
    cudaGetSymbolAddress((void**)&hh, g_hh);
    cudaGetSymbolAddress((void**)&hl, g_hl);
    cudaGetSymbolAddress((void**)&wh, g_wh);
    cudaGetSymbolAddress((void**)&wl, g_wl);

    cudaFuncSetAttribute(gemm_qkv6,   cudaFuncAttributeMaxDynamicSharedMemorySize, QKV_SMEM);
    cudaFuncSetAttribute(gemm_mma<1>, cudaFuncAttributeMaxDynamicSharedMemorySize, GEMM_SMEM);
    cudaFuncSetAttribute(gemm_mma<2>, cudaFuncAttributeMaxDynamicSharedMemorySize, GEMM_SMEM);
    cudaFuncSetAttribute(gemm_wo_pair, cudaFuncAttributeMaxDynamicSharedMemorySize, GEMM_SMEM);
    cudaFuncSetAttribute(spatial_attn, cudaFuncAttributeMaxDynamicSharedMemorySize, SA_SMEM);
    cudaFuncSetAttribute(temporal_attn, cudaFuncAttributeMaxDynamicSharedMemorySize, TEMP_SMEM_BYTES);

    // ---- conversions ----
    split_f32_kernel<<<NTOT / 4 / 256, 256>>>(x, xh, xl, NTOT / 4);
    WPtrs wp;
    wp.p[0] = (const float*)d_in[1];
    wp.p[1] = (const float*)d_in[2];
    wp.p[2] = (const float*)d_in[3];
    wp.p[3] = (const float*)d_in[4];
    wp.p[4] = (const float*)d_in[5];
    wp.p[5] = (const float*)d_in[6];
    wp.p[6] = (const float*)d_in[7];
    wp.p[7] = (const float*)d_in[8];
    wp.p[8] = (const float*)d_in[11];
    wp.p[9] = (const float*)d_in[13];
    convert_weights_t<<<dim3(64, CC, NW), 256>>>(wp, wh, wl);

    // ---- fused q/k/v projections (both branches) ----
    Out6 o6;
    o6.y[0] = qs; o6.y[1] = ks; o6.y[2] = vs;
    o6.y[3] = qt; o6.y[4] = kt; o6.y[5] = vt;
    gemm_qkv6<<<dim3(BB, 2, CC), 256, QKV_SMEM>>>(xh, xl, wh, wl, o6);

    // ---- attentions ----
    spatial_attn<<<dim3(SS, BB), 768, SA_SMEM>>>(qs, ks, vs, ah, al);
    temporal_attn<<<dim3(CC, HH, BB), 256, TEMP_SMEM_BYTES>>>(qt, kt, vt, hh, hl);

    // ---- output projections (merged dual launch) ----
    gemm_wo_pair<<<dim3(BB, 2, 2 * CC), 256, GEMM_SMEM>>>(
        ah, al, wh + 3*(size_t)WELEMS, wl + 3*(size_t)WELEMS, spat,
        hh, hl, wh + 7*(size_t)WELEMS, wl + 7*(size_t)WELEMS, temp);

    // ---- residual + dual LN (emits attn fp32 + bf16 pair) ----
    dual_ln<<<NROWS, 256>>>(x, spat, temp, ln_g, ln_b, attn, ah, al);

    // ---- per-joint FF + final LN ----
    gemm_mma<1><<<dim3(BB, 2, CC), 256, GEMM_SMEM>>>(ah, al, wh + 8*(size_t)WELEMS, wl + 8*(size_t)WELEMS, ff_b1, nullptr, hh, hl);
    gemm_mma<2><<<dim3(BB, 2, CC), 256, GEMM_SMEM>>>(hh, hl, wh + 9*(size_t)WELEMS, wl + 9*(size_t)WELEMS, ff_b2, ffo, nullptr, nullptr);
    final_ln<<<NROWS, 256>>>(attn, ffo, ln_g, ln_b, out);
}